// round 6
// baseline (speedup 1.0000x reference)
#include <cuda_runtime.h>
#include <cuda_fp16.h>

#define N_NODES 50000
#define N_EDGES 800000
#define DIN 128
#define DHID 128
#define NH 8
#define DK 16
#define TN 8
#define TE 8
#define NB 4
#define NCHUNK ((N_NODES + 1023) / 1024)

// ---------------- scratch (static device memory; no allocations) ----------------
__device__ float  g_W[4 * TN * DIN * DHID];            // Wk,Wq,Wv,Wa  [4][8][128*128]
__device__ float  g_kqv[3 * NH * N_NODES * DK];        // k,q,v in [mat][h][n][16] layout
__device__ __half g_k_h[(size_t)NH * N_NODES * DK];    // k fp16 [h][n][16], 12.8 MB (L2-resident)
__device__ __half g_qt_h[(size_t)NH * N_NODES * TE * DK]; // (att@q)*pri*scale fp16 [h][n][et][16], 102.4MB
__device__ __half g_vt_h[(size_t)TE * NH * N_NODES * DK]; // v@msg fp16 [et*NH+h][n][16], 102.4 MB
__device__ float  g_elog[(size_t)NH * N_EDGES];        // logits -> exp values [h][p]
__device__ int    g_mkey[N_NODES * NH];                // max logit per (dst,h), monotone int key
__device__ float  g_agg[N_NODES * DHID];               // aggregated messages [n][128]
__device__ int    g_deg[N_NODES];
__device__ int    g_rowstart[N_NODES + 1];
__device__ int    g_cursor[N_NODES];
__device__ int    g_eidx[N_EDGES];                     // (et<<16)|src, sorted by dst
__device__ int    g_dst_s[N_EDGES];                    // dst, sorted (CSR order)
__device__ int    g_node_order[N_NODES];
__device__ int    g_ncount[TN];
__device__ int    g_tstart[TN + 1];
__device__ int    g_tcur[TN];
__device__ int    g_part[NCHUNK];
__device__ int    g_chunkoff[NCHUNK];

// monotone float<->int key (order-preserving, so atomicMax is deterministic)
__device__ __forceinline__ int   fkey(float f) { int b = __float_as_int(f); return b >= 0 ? b : (b ^ 0x7FFFFFFF); }
__device__ __forceinline__ float fdec(int k)   { return __int_as_float(k >= 0 ? k : (k ^ 0x7FFFFFFF)); }

// ---------------- init: zero counters, -inf max keys ----------------
__global__ void k_init() {
    int i = blockIdx.x * blockDim.x + threadIdx.x;
    if (i < N_NODES) g_deg[i] = 0;
    if (i < TN) g_ncount[i] = 0;
    if (i < N_NODES * NH) g_mkey[i] = 0x80000000;   // INT_MIN <= every key
}

// ---------------- build per-type weight matrices W[t] = comp[t] @ basis ----------------
__global__ void k_prepW(const float* __restrict__ ck, const float* __restrict__ bk,
                        const float* __restrict__ cq, const float* __restrict__ bq,
                        const float* __restrict__ cv, const float* __restrict__ bv,
                        const float* __restrict__ ca, const float* __restrict__ ba) {
    int idx = blockIdx.x * blockDim.x + threadIdx.x;           // 4 * 8 * 16384
    if (idx >= 4 * TN * DIN * DHID) return;
    int m  = idx >> 17;           // matrix id
    int r  = idx & 131071;
    int t  = r >> 14;             // type
    int io = r & 16383;
    const float* comp;
    const float* basis;
    if (m == 0)      { comp = ck; basis = bk; }
    else if (m == 1) { comp = cq; basis = bq; }
    else if (m == 2) { comp = cv; basis = bv; }
    else             { comp = ca; basis = ba; }
    float acc = 0.f;
#pragma unroll
    for (int b = 0; b < NB; b++)
        acc += comp[t * NB + b] * basis[b * (DIN * DHID) + io];
    g_W[idx] = acc;
}

// ---------------- counts: node types + in-degrees ----------------
__global__ void k_count(const int* __restrict__ ntype, const int* __restrict__ dst) {
    int i = blockIdx.x * blockDim.x + threadIdx.x;
    if (i < N_NODES) atomicAdd(&g_ncount[ntype[i]], 1);
    if (i < N_EDGES) atomicAdd(&g_deg[dst[i]], 1);
}

// ---------------- parallel scan phase A: per-chunk exclusive scan + chunk totals ----------------
__global__ void k_scanA() {
    __shared__ int wsum[32];
    int tid = threadIdx.x;
    int chunk = blockIdx.x;
    int i = chunk * 1024 + tid;
    int v = (i < N_NODES) ? g_deg[i] : 0;
    int lane = tid & 31, w = tid >> 5;
    int s = v;
#pragma unroll
    for (int o = 1; o < 32; o <<= 1) {
        int t = __shfl_up_sync(0xffffffffu, s, o);
        if (lane >= o) s += t;
    }
    if (lane == 31) wsum[w] = s;
    __syncthreads();
    if (w == 0) {
        int x = wsum[lane];
#pragma unroll
        for (int o = 1; o < 32; o <<= 1) {
            int t = __shfl_up_sync(0xffffffffu, x, o);
            if (lane >= o) x += t;
        }
        wsum[lane] = x;
    }
    __syncthreads();
    int excl = s - v + (w > 0 ? wsum[w - 1] : 0);
    if (i < N_NODES) g_rowstart[i] = excl;
    if (tid == 1023) g_part[chunk] = excl + v;
}

// ---------------- scan phase B: tiny serial scan of chunk totals + type offsets ----------------
__global__ void k_scanB() {
    if (threadIdx.x == 0) {
        int acc = 0;
        for (int c = 0; c < NCHUNK; c++) { g_chunkoff[c] = acc; acc += g_part[c]; }
        g_rowstart[N_NODES] = N_EDGES;
        int a2 = 0;
        g_tstart[0] = 0;
        for (int t = 0; t < TN; t++) { a2 += g_ncount[t]; g_tstart[t + 1] = a2; }
        for (int t = 0; t < TN; t++) g_tcur[t] = g_tstart[t];
    }
}

// ---------------- scan phase C: add chunk offsets, init cursors ----------------
__global__ void k_scanC() {
    int i = blockIdx.x * 1024 + threadIdx.x;
    if (i < N_NODES) {
        int r = g_rowstart[i] + g_chunkoff[blockIdx.x];
        g_rowstart[i] = r;
        g_cursor[i] = r;
    }
}

// ---------------- scatter: node order by type, edge metadata into CSR order ----------------
__global__ void k_scatter(const int* __restrict__ ntype, const int* __restrict__ src,
                          const int* __restrict__ dst, const int* __restrict__ etype) {
    int i = blockIdx.x * blockDim.x + threadIdx.x;
    if (i < N_NODES) {
        int t = ntype[i];
        int p = atomicAdd(&g_tcur[t], 1);
        g_node_order[p] = i;
    }
    if (i < N_EDGES) {
        int d = dst[i];
        int p = atomicAdd(&g_cursor[d], 1);
        g_eidx[p] = (etype[i] << 16) | src[i];    // N_NODES < 65536
        g_dst_s[p] = d;
    }
}

// ---------------- projection GEMM: k,q,v = x @ W{k,q,v}[t], type-grouped ----------------
// also emits fp16 copy of k into g_k_h (L2-resident gather target for logits)
__global__ void k_proj(const float* __restrict__ x) {
    int t = blockIdx.y;
    int cnt = g_tstart[t + 1] - g_tstart[t];
    int tile = blockIdx.x * 64;
    if (tile >= cnt) return;

    __shared__ __align__(16) float xs[64][132];
    __shared__ __align__(16) float ws[16][128];
    __shared__ int rows[64];

    int tid = threadIdx.x;
    if (tid < 64) {
        int r = tile + tid;
        rows[tid] = (r < cnt) ? g_node_order[g_tstart[t] + r] : -1;
    }
    __syncthreads();

    for (int i = tid; i < 64 * 32; i += 256) {
        int nr = i >> 5, c4 = i & 31;
        float4 v = make_float4(0.f, 0.f, 0.f, 0.f);
        int g = rows[nr];
        if (g >= 0) v = ((const float4*)x)[g * 32 + c4];
        *((float4*)&xs[nr][c4 * 4]) = v;
    }

    int tc = tid & 31, tr = tid >> 5;
    int h = tc >> 2, j = (tc & 3) * 4;

    for (int mat = 0; mat < 3; mat++) {
        const float* W = g_W + (mat * TN + t) * (DIN * DHID);
        float acc[8][4];
#pragma unroll
        for (int m = 0; m < 8; m++)
#pragma unroll
            for (int c = 0; c < 4; c++) acc[m][c] = 0.f;

        for (int kk = 0; kk < 8; kk++) {
            __syncthreads();
            for (int i = tid; i < 512; i += 256) {
                int r = i >> 5, c4 = i & 31;
                ((float4*)&ws[r][0])[c4] = ((const float4*)(W + (kk * 16 + r) * DHID))[c4];
            }
            __syncthreads();
#pragma unroll
            for (int k2 = 0; k2 < 16; k2++) {
                float4 b = *((const float4*)&ws[k2][tc * 4]);
#pragma unroll
                for (int m = 0; m < 8; m++) {
                    float a = xs[tr * 8 + m][kk * 16 + k2];
                    acc[m][0] += a * b.x; acc[m][1] += a * b.y;
                    acc[m][2] += a * b.z; acc[m][3] += a * b.w;
                }
            }
        }
        float* outb = g_kqv + (mat * NH + h) * (N_NODES * DK);
#pragma unroll
        for (int m = 0; m < 8; m++) {
            int g = rows[tr * 8 + m];
            if (g >= 0) {
                float4 o = make_float4(acc[m][0], acc[m][1], acc[m][2], acc[m][3]);
                *((float4*)&outb[g * DK + j]) = o;
                if (mat == 0) {
                    __half2 h0 = __floats2half2_rn(acc[m][0], acc[m][1]);
                    __half2 h1 = __floats2half2_rn(acc[m][2], acc[m][3]);
                    __half2* kp = (__half2*)(g_k_h + ((size_t)h * N_NODES + g) * DK + j);
                    kp[0] = h0; kp[1] = h1;
                }
            }
        }
    }
}

// ---------------- qt: qt[h,n,et,:] = (att[et,h] @ q[n,h]) * pri * scale, fp16 ----------------
__global__ void k_qt(const float* __restrict__ att, const float* __restrict__ pri) {
    int lane = threadIdx.x & 31;
    int h = threadIdx.x >> 5;
    int node = blockIdx.x * 32 + lane;
    if (node >= N_NODES) return;

    const float4* qp = (const float4*)(g_kqv + (1 * NH + h) * (N_NODES * DK) + node * DK);
    float4 q0 = qp[0], q1 = qp[1], q2 = qp[2], q3 = qp[3];

    __half* outb = g_qt_h + ((size_t)h * N_NODES + node) * (TE * DK);
    for (int t = 0; t < TE; t++) {
        float pv = pri[t * NH + h] * 0.25f;
        const float4* A = (const float4*)att + (t * NH + h) * 64;   // lane-uniform broadcasts
        __align__(16) __half2 hq[8];
#pragma unroll
        for (int ip = 0; ip < 8; ip++) {
            int i0 = 2 * ip, i1 = 2 * ip + 1;
            float4 a0 = A[i0 * 4 + 0], a1 = A[i0 * 4 + 1], a2 = A[i0 * 4 + 2], a3 = A[i0 * 4 + 3];
            float r0 = a0.x * q0.x + a0.y * q0.y + a0.z * q0.z + a0.w * q0.w
                     + a1.x * q1.x + a1.y * q1.y + a1.z * q1.z + a1.w * q1.w
                     + a2.x * q2.x + a2.y * q2.y + a2.z * q2.z + a2.w * q2.w
                     + a3.x * q3.x + a3.y * q3.y + a3.z * q3.z + a3.w * q3.w;
            float4 b0 = A[i1 * 4 + 0], b1 = A[i1 * 4 + 1], b2 = A[i1 * 4 + 2], b3 = A[i1 * 4 + 3];
            float r1 = b0.x * q0.x + b0.y * q0.y + b0.z * q0.z + b0.w * q0.w
                     + b1.x * q1.x + b1.y * q1.y + b1.z * q1.z + b1.w * q1.w
                     + b2.x * q2.x + b2.y * q2.y + b2.z * q2.z + b2.w * q2.w
                     + b3.x * q3.x + b3.y * q3.y + b3.z * q3.z + b3.w * q3.w;
            hq[ip] = __floats2half2_rn(r0 * pv, r1 * pv);
        }
        *((uint4*)(outb + t * DK))     = *((uint4*)&hq[0]);
        *((uint4*)(outb + t * DK + 8)) = *((uint4*)&hq[4]);
    }
}

// ---------------- relation projection (v only): vt[et*NH+h, n] = v@msg, fp16 ----------------
__global__ void k_relproj(const float* __restrict__ msg) {
    int lane = threadIdx.x & 31;
    int h = threadIdx.x >> 5;
    int node = blockIdx.x * 32 + lane;
    if (node >= N_NODES) return;

    float vreg[16];
    const float4* vp = (const float4*)(g_kqv + (2 * NH + h) * (N_NODES * DK) + node * DK);
#pragma unroll
    for (int c = 0; c < 4; c++) {
        float4 b = vp[c];
        vreg[c * 4 + 0] = b.x; vreg[c * 4 + 1] = b.y; vreg[c * 4 + 2] = b.z; vreg[c * 4 + 3] = b.w;
    }

    for (int t = 0; t < TE; t++) {
        float vt[16];
#pragma unroll
        for (int z = 0; z < 16; z++) vt[z] = 0.f;
        const float4* M = (const float4*)msg + (t * NH + h) * 64;
#pragma unroll
        for (int i = 0; i < 16; i++) {
            float vi = vreg[i];
#pragma unroll
            for (int jc = 0; jc < 4; jc++) {
                float4 mm = M[i * 4 + jc];
                vt[jc * 4 + 0] += vi * mm.x; vt[jc * 4 + 1] += vi * mm.y;
                vt[jc * 4 + 2] += vi * mm.z; vt[jc * 4 + 3] += vi * mm.w;
            }
        }
        __align__(16) __half2 hv[8];
#pragma unroll
        for (int c = 0; c < 8; c++)
            hv[c] = __floats2half2_rn(vt[2 * c], vt[2 * c + 1]);
        size_t off = ((size_t)(t * NH + h) * N_NODES + node) * DK;
        *((uint4*)&g_vt_h[off])     = *((uint4*)&hv[0]);
        *((uint4*)&g_vt_h[off + 8]) = *((uint4*)&hv[4]);
    }
}

// ---------------- edge attention logits: k (L2-resident) . qt (L1-local) ----------------
__global__ void k_logits() {
    int p = blockIdx.x * blockDim.x + threadIdx.x;
    int h = blockIdx.y;
    if (p >= N_EDGES) return;
    int e = g_eidx[p];
    int et = e >> 16, s = e & 0xFFFF;
    int d = g_dst_s[p];
    const __half2* kk = (const __half2*)(g_k_h + ((size_t)h * N_NODES + s) * DK);
    const __half2* qt = (const __half2*)(g_qt_h + (((size_t)h * N_NODES + d) * TE + et) * DK);
    float acc = 0.f;
#pragma unroll
    for (int c = 0; c < 8; c++) {
        float2 a = __half22float2(kk[c]);
        float2 b = __half22float2(qt[c]);
        acc += a.x * b.x + a.y * b.y;
    }
    g_elog[(size_t)h * N_EDGES + p] = acc;
    atomicMax(&g_mkey[d * NH + h], fkey(acc));   // order-independent -> deterministic
}

// ---------------- edge softmax + aggregation (exp once; 4 edges in flight) ----------------
__global__ void k_agg() {
    int d = blockIdx.x;
    int h = threadIdx.x >> 5;
    int lane = threadIdx.x & 31;
    int rs = g_rowstart[d];
    int deg = g_rowstart[d + 1] - rs;
    int j2 = lane & 7, quad = lane >> 3;
    float* el = g_elog + (size_t)h * N_EDGES + rs;

    if (deg == 0) {
        if (lane < 8) ((float2*)&g_agg[d * DHID + h * DK])[j2] = make_float2(0.f, 0.f);
        return;
    }
    float m = fdec(g_mkey[d * NH + h]);
    // pass 1: exp once (cache into elog) + denom
    float s = 0.f;
    for (int i = lane; i < deg; i += 32) {
        float v = __expf(el[i] - m);
        el[i] = v;
        s += v;
    }
#pragma unroll
    for (int o = 16; o > 0; o >>= 1) s += __shfl_xor_sync(0xffffffffu, s, o);
    float inv = 1.f / s;
    // pass 2: weighted sum of fp16 vt (4 edges in flight; each lane covers 2 j's)
    float ax = 0.f, ay = 0.f;
    for (int i = quad; i < deg; i += 4) {
        float a = el[i];
        int e = g_eidx[rs + i];
        int et = e >> 16, sn = e & 0xFFFF;
        __half2 v = *((const __half2*)(g_vt_h + ((size_t)(et * NH + h) * N_NODES + sn) * DK) + j2);
        float2 vf = __half22float2(v);
        ax += a * vf.x; ay += a * vf.y;
    }
#pragma unroll
    for (int o = 16; o >= 8; o >>= 1) {
        ax += __shfl_xor_sync(0xffffffffu, ax, o);
        ay += __shfl_xor_sync(0xffffffffu, ay, o);
    }
    if (lane < 8) ((float2*)&g_agg[d * DHID + h * DK])[j2] = make_float2(ax * inv, ay * inv);
}

// ---------------- output: relu(agg @ Wa[t] + x @ loop + bias) ----------------
__global__ void k_out(const float* __restrict__ x, const float* __restrict__ loopw,
                      const float* __restrict__ bias, float* __restrict__ out) {
    int t = blockIdx.y;
    int cnt = g_tstart[t + 1] - g_tstart[t];
    int tile = blockIdx.x * 64;
    if (tile >= cnt) return;

    __shared__ __align__(16) float xs[64][132];
    __shared__ __align__(16) float ws[16][128];
    __shared__ int rows[64];

    int tid = threadIdx.x;
    if (tid < 64) {
        int r = tile + tid;
        rows[tid] = (r < cnt) ? g_node_order[g_tstart[t] + r] : -1;
    }
    __syncthreads();

    int tc = tid & 31, tr = tid >> 5;
    float acc[8][4];
#pragma unroll
    for (int m = 0; m < 8; m++)
#pragma unroll
        for (int c = 0; c < 4; c++) acc[m][c] = 0.f;

    for (int ph = 0; ph < 2; ph++) {
        const float* A = (ph == 0) ? g_agg : x;
        const float* W = (ph == 0) ? (g_W + (3 * TN + t) * (DIN * DHID)) : loopw;
        __syncthreads();
        for (int i = tid; i < 64 * 32; i += 256) {
            int nr = i >> 5, c4 = i & 31;
            float4 v = make_float4(0.f, 0.f, 0.f, 0.f);
            int g = rows[nr];
            if (g >= 0) v = ((const float4*)A)[g * 32 + c4];
            *((float4*)&xs[nr][c4 * 4]) = v;
        }
        for (int kk = 0; kk < 8; kk++) {
            __syncthreads();
            for (int i = tid; i < 512; i += 256) {
                int r = i >> 5, c4 = i & 31;
                ((float4*)&ws[r][0])[c4] = ((const float4*)(W + (kk * 16 + r) * DHID))[c4];
            }
            __syncthreads();
#pragma unroll
            for (int k2 = 0; k2 < 16; k2++) {
                float4 b = *((const float4*)&ws[k2][tc * 4]);
#pragma unroll
                for (int m = 0; m < 8; m++) {
                    float a = xs[tr * 8 + m][kk * 16 + k2];
                    acc[m][0] += a * b.x; acc[m][1] += a * b.y;
                    acc[m][2] += a * b.z; acc[m][3] += a * b.w;
                }
            }
        }
    }

    float4 bv = *((const float4*)&bias[tc * 4]);
#pragma unroll
    for (int m = 0; m < 8; m++) {
        int g = rows[tr * 8 + m];
        if (g >= 0) {
            float4 o;
            o.x = fmaxf(acc[m][0] + bv.x, 0.f);
            o.y = fmaxf(acc[m][1] + bv.y, 0.f);
            o.z = fmaxf(acc[m][2] + bv.z, 0.f);
            o.w = fmaxf(acc[m][3] + bv.w, 0.f);
            *((float4*)&out[g * DHID + tc * 4]) = o;
        }
    }
}

// ---------------- launch ----------------
extern "C" void kernel_launch(void* const* d_in, const int* in_sizes, int n_in,
                              void* d_out, int out_size) {
    const float* x     = (const float*)d_in[0];
    const int*   ntype = (const int*)d_in[1];
    const int*   src   = (const int*)d_in[2];
    const int*   dst   = (const int*)d_in[3];
    const int*   etype = (const int*)d_in[4];
    const float* wck   = (const float*)d_in[5];
    const float* wbk   = (const float*)d_in[6];
    const float* wcq   = (const float*)d_in[7];
    const float* wbq   = (const float*)d_in[8];
    const float* wcv   = (const float*)d_in[9];
    const float* wbv   = (const float*)d_in[10];
    const float* wca   = (const float*)d_in[11];
    const float* wba   = (const float*)d_in[12];
    const float* pri   = (const float*)d_in[13];
    const float* att   = (const float*)d_in[14];
    const float* msg   = (const float*)d_in[15];
    const float* loopw = (const float*)d_in[16];
    const float* bias  = (const float*)d_in[17];
    float* out = (float*)d_out;

    k_init<<<(N_NODES * NH + 255) / 256, 256>>>();
    k_prepW<<<(4 * TN * DIN * DHID + 255) / 256, 256>>>(wck, wbk, wcq, wbq, wcv, wbv, wca, wba);
    k_count<<<(N_EDGES + 255) / 256, 256>>>(ntype, dst);
    k_scanA<<<NCHUNK, 1024>>>();
    k_scanB<<<1, 32>>>();
    k_scanC<<<NCHUNK, 1024>>>();
    k_scatter<<<(N_EDGES + 255) / 256, 256>>>(ntype, src, dst, etype);
    k_proj<<<dim3((N_NODES + 63) / 64, TN), 256>>>(x);
    k_qt<<<(N_NODES + 31) / 32, 256>>>(att, pri);
    k_relproj<<<(N_NODES + 31) / 32, 256>>>(msg);
    k_logits<<<dim3((N_EDGES + 255) / 256, NH), 256>>>();
    k_agg<<<N_NODES, 256>>>();
    k_out<<<dim3((N_NODES + 63) / 64, TN), 256>>>(x, loopw, bias, out);
}

// round 8
// speedup vs baseline: 1.1133x; 1.1133x over previous
#include <cuda_runtime.h>
#include <cuda_fp16.h>
#include <cstdint>

#define N_NODES 50000
#define N_EDGES 800000
#define DIN 128
#define DHID 128
#define NH 8
#define DK 16
#define TN 8
#define TE 8
#define NB 4
#define NCHUNK ((N_NODES + 1023) / 1024)

// ---------------- scratch (static device memory; no allocations) ----------------
__device__ float  g_W[4 * TN * DIN * DHID];            // Wk,Wq,Wv,Wa  [4][8][128*128]
__device__ __half g_W_h[3 * TN * DIN * DHID];          // fp16 Wk,Wq,Wv for tensor cores
__device__ float  g_kqv[3 * NH * N_NODES * DK];        // k,q,v in [mat][h][n][16] layout
__device__ __half g_k_h[(size_t)NH * N_NODES * DK];    // k fp16 [h][n][16], 12.8 MB (L2-resident)
__device__ __half g_qt_h[(size_t)NH * N_NODES * TE * DK]; // (att@q)*pri*scale fp16 [h][n][et][16]
__device__ __half g_vt_h[(size_t)TE * NH * N_NODES * DK]; // v@msg fp16 [et*NH+h][n][16]
__device__ float  g_elog[(size_t)NH * N_EDGES];        // logits -> exp values [h][p]
__device__ int    g_mkey[N_NODES * NH];                // max logit per (dst,h), monotone int key
__device__ float  g_agg[N_NODES * DHID];               // aggregated messages [n][128]
__device__ int    g_deg[N_NODES];
__device__ int    g_rowstart[N_NODES + 1];
__device__ int    g_cursor[N_NODES];
__device__ int    g_eidx[N_EDGES];                     // (et<<16)|src, sorted by dst
__device__ int    g_dst_s[N_EDGES];                    // dst, sorted (CSR order)
__device__ int    g_node_order[N_NODES];
__device__ int    g_ncount[TN];
__device__ int    g_tstart[TN + 1];
__device__ int    g_tcur[TN];
__device__ int    g_part[NCHUNK];
__device__ int    g_chunkoff[NCHUNK];

// monotone float<->int key (order-preserving, so atomicMax is deterministic)
__device__ __forceinline__ int   fkey(float f) { int b = __float_as_int(f); return b >= 0 ? b : (b ^ 0x7FFFFFFF); }
__device__ __forceinline__ float fdec(int k)   { return __int_as_float(k >= 0 ? k : (k ^ 0x7FFFFFFF)); }

// ---------------- warp-mma helpers ----------------
__device__ __forceinline__ void ldsm_x4(unsigned& r0, unsigned& r1, unsigned& r2, unsigned& r3, unsigned addr) {
    asm volatile("ldmatrix.sync.aligned.m8n8.x4.shared.b16 {%0,%1,%2,%3}, [%4];"
                 : "=r"(r0), "=r"(r1), "=r"(r2), "=r"(r3) : "r"(addr));
}
__device__ __forceinline__ void ldsm_x4_t(unsigned& r0, unsigned& r1, unsigned& r2, unsigned& r3, unsigned addr) {
    asm volatile("ldmatrix.sync.aligned.m8n8.x4.trans.shared.b16 {%0,%1,%2,%3}, [%4];"
                 : "=r"(r0), "=r"(r1), "=r"(r2), "=r"(r3) : "r"(addr));
}
__device__ __forceinline__ void mma16816(float* c, unsigned a0, unsigned a1, unsigned a2, unsigned a3,
                                         unsigned b0, unsigned b1) {
    asm volatile("mma.sync.aligned.m16n8k16.row.col.f32.f16.f16.f32 "
                 "{%0,%1,%2,%3},{%4,%5,%6,%7},{%8,%9},{%0,%1,%2,%3};"
                 : "+f"(c[0]), "+f"(c[1]), "+f"(c[2]), "+f"(c[3])
                 : "r"(a0), "r"(a1), "r"(a2), "r"(a3), "r"(b0), "r"(b1));
}

// ---------------- init: zero counters, -inf max keys ----------------
__global__ void k_init() {
    int i = blockIdx.x * blockDim.x + threadIdx.x;
    if (i < N_NODES) g_deg[i] = 0;
    if (i < TN) g_ncount[i] = 0;
    if (i < N_NODES * NH) g_mkey[i] = 0x80000000;   // INT_MIN <= every key
}

// ---------------- build per-type weight matrices W[t] = comp[t] @ basis ----------------
__global__ void k_prepW(const float* __restrict__ ck, const float* __restrict__ bk,
                        const float* __restrict__ cq, const float* __restrict__ bq,
                        const float* __restrict__ cv, const float* __restrict__ bv,
                        const float* __restrict__ ca, const float* __restrict__ ba) {
    int idx = blockIdx.x * blockDim.x + threadIdx.x;           // 4 * 8 * 16384
    if (idx >= 4 * TN * DIN * DHID) return;
    int m  = idx >> 17;           // matrix id
    int r  = idx & 131071;
    int t  = r >> 14;             // type
    int io = r & 16383;
    const float* comp;
    const float* basis;
    if (m == 0)      { comp = ck; basis = bk; }
    else if (m == 1) { comp = cq; basis = bq; }
    else if (m == 2) { comp = cv; basis = bv; }
    else             { comp = ca; basis = ba; }
    float acc = 0.f;
#pragma unroll
    for (int b = 0; b < NB; b++)
        acc += comp[t * NB + b] * basis[b * (DIN * DHID) + io];
    g_W[idx] = acc;
    if (m < 3) g_W_h[idx] = __float2half(acc);
}

// ---------------- counts: node types + in-degrees ----------------
__global__ void k_count(const int* __restrict__ ntype, const int* __restrict__ dst) {
    int i = blockIdx.x * blockDim.x + threadIdx.x;
    if (i < N_NODES) atomicAdd(&g_ncount[ntype[i]], 1);
    if (i < N_EDGES) atomicAdd(&g_deg[dst[i]], 1);
}

// ---------------- parallel scan phase A ----------------
__global__ void k_scanA() {
    __shared__ int wsum[32];
    int tid = threadIdx.x;
    int chunk = blockIdx.x;
    int i = chunk * 1024 + tid;
    int v = (i < N_NODES) ? g_deg[i] : 0;
    int lane = tid & 31, w = tid >> 5;
    int s = v;
#pragma unroll
    for (int o = 1; o < 32; o <<= 1) {
        int t = __shfl_up_sync(0xffffffffu, s, o);
        if (lane >= o) s += t;
    }
    if (lane == 31) wsum[w] = s;
    __syncthreads();
    if (w == 0) {
        int x = wsum[lane];
#pragma unroll
        for (int o = 1; o < 32; o <<= 1) {
            int t = __shfl_up_sync(0xffffffffu, x, o);
            if (lane >= o) x += t;
        }
        wsum[lane] = x;
    }
    __syncthreads();
    int excl = s - v + (w > 0 ? wsum[w - 1] : 0);
    if (i < N_NODES) g_rowstart[i] = excl;
    if (tid == 1023) g_part[chunk] = excl + v;
}

// ---------------- scan phase B ----------------
__global__ void k_scanB() {
    if (threadIdx.x == 0) {
        int acc = 0;
        for (int c = 0; c < NCHUNK; c++) { g_chunkoff[c] = acc; acc += g_part[c]; }
        g_rowstart[N_NODES] = N_EDGES;
        int a2 = 0;
        g_tstart[0] = 0;
        for (int t = 0; t < TN; t++) { a2 += g_ncount[t]; g_tstart[t + 1] = a2; }
        for (int t = 0; t < TN; t++) g_tcur[t] = g_tstart[t];
    }
}

// ---------------- scan phase C ----------------
__global__ void k_scanC() {
    int i = blockIdx.x * 1024 + threadIdx.x;
    if (i < N_NODES) {
        int r = g_rowstart[i] + g_chunkoff[blockIdx.x];
        g_rowstart[i] = r;
        g_cursor[i] = r;
    }
}

// ---------------- scatter ----------------
__global__ void k_scatter(const int* __restrict__ ntype, const int* __restrict__ src,
                          const int* __restrict__ dst, const int* __restrict__ etype) {
    int i = blockIdx.x * blockDim.x + threadIdx.x;
    if (i < N_NODES) {
        int t = ntype[i];
        int p = atomicAdd(&g_tcur[t], 1);
        g_node_order[p] = i;
    }
    if (i < N_EDGES) {
        int d = dst[i];
        int p = atomicAdd(&g_cursor[d], 1);
        g_eidx[p] = (etype[i] << 16) | src[i];    // N_NODES < 65536
        g_dst_s[p] = d;
    }
}

// ---------------- projection GEMM via tensor cores (fp16 in, fp32 accum) ----------------
// tile: 64 nodes x 128 out, K=128 in 2 chunks of 64. 8 warps = 4M x 2N.
__global__ void k_proj(const float* __restrict__ x) {
    int t = blockIdx.y;
    int cnt = g_tstart[t + 1] - g_tstart[t];
    int tile = blockIdx.x * 64;
    if (tile >= cnt) return;

    __shared__ __align__(16) __half As[64][136];
    __shared__ __align__(16) __half Ws[64][136];
    __shared__ int rows[64];

    int tid = threadIdx.x;
    if (tid < 64) {
        int r = tile + tid;
        rows[tid] = (r < cnt) ? g_node_order[g_tstart[t] + r] : -1;
    }
    __syncthreads();

    // gathered x rows -> fp16 smem
    for (int i = tid; i < 64 * 32; i += 256) {
        int nr = i >> 5;
        int c4 = i & 31;
        float4 v = make_float4(0.f, 0.f, 0.f, 0.f);
        int g = rows[nr];
        if (g >= 0) v = ((const float4*)x)[g * 32 + c4];
        *((__half2*)&As[nr][c4 * 4])     = __floats2half2_rn(v.x, v.y);
        *((__half2*)&As[nr][c4 * 4 + 2]) = __floats2half2_rn(v.z, v.w);
    }

    int w = tid >> 5;
    int lane = tid & 31;
    int mr = (w & 3) * 16;            // M offset of this warp
    int nc = (w >> 2) * 64;           // N offset of this warp
    int lrow = (lane & 7) + ((lane >> 3) & 1) * 8;   // ldmatrix source row (within 16)
    int lcol8 = (lane >> 4) * 8;                     // ldmatrix 8-col group

    int r0 = mr + (lane >> 2);        // accumulator row (mma layout)
    int cb = nc + (lane & 3) * 2;     // accumulator col base

    for (int mat = 0; mat < 3; mat++) {
        float acc[8][4];
#pragma unroll
        for (int nt = 0; nt < 8; nt++) {
#pragma unroll
            for (int c = 0; c < 4; c++) acc[nt][c] = 0.f;
        }

        const __half* W = g_W_h + (mat * TN + t) * (DIN * DHID);
        for (int kc = 0; kc < 2; kc++) {
            __syncthreads();   // protects Ws rewrite (and As on first pass)
            for (int i = tid; i < 64 * 16; i += 256) {
                int r = i >> 4;
                int c8 = i & 15;
                *((uint4*)&Ws[r][c8 * 8]) = ((const uint4*)(W + (kc * 64 + r) * DHID))[c8];
            }
            __syncthreads();
#pragma unroll
            for (int ks = 0; ks < 4; ks++) {
                unsigned a0, a1, a2, a3;
                unsigned aAddr = (unsigned)__cvta_generic_to_shared(
                    &As[mr + lrow][kc * 64 + ks * 16 + lcol8]);
                ldsm_x4(a0, a1, a2, a3, aAddr);
#pragma unroll
                for (int np = 0; np < 4; np++) {
                    unsigned b0, b1, b2, b3;
                    unsigned bAddr = (unsigned)__cvta_generic_to_shared(
                        &Ws[ks * 16 + lrow][nc + np * 16 + lcol8]);
                    ldsm_x4_t(b0, b1, b2, b3, bAddr);
                    mma16816(acc[np * 2],     a0, a1, a2, a3, b0, b1);
                    mma16816(acc[np * 2 + 1], a0, a1, a2, a3, b2, b3);
                }
            }
        }
        // store: [mat][h][n][16] fp32 (+ fp16 k copy)
        int g0 = rows[r0];
        int g1 = rows[r0 + 8];
        float* outb = g_kqv + mat * NH * (N_NODES * DK);
#pragma unroll
        for (int nt = 0; nt < 8; nt++) {
            int c = cb + nt * 8;
            int h = c >> 4;
            int j = c & 15;
            if (g0 >= 0) {
                *((float2*)&outb[(h * N_NODES + g0) * DK + j]) = make_float2(acc[nt][0], acc[nt][1]);
                if (mat == 0) {
                    *((__half2*)&g_k_h[((size_t)h * N_NODES + g0) * DK + j]) =
                        __floats2half2_rn(acc[nt][0], acc[nt][1]);
                }
            }
            if (g1 >= 0) {
                *((float2*)&outb[(h * N_NODES + g1) * DK + j]) = make_float2(acc[nt][2], acc[nt][3]);
                if (mat == 0) {
                    *((__half2*)&g_k_h[((size_t)h * N_NODES + g1) * DK + j]) =
                        __floats2half2_rn(acc[nt][2], acc[nt][3]);
                }
            }
        }
    }
}

// ---------------- qt: qt[h,n,et,:] = (att[et,h] @ q[n,h]) * pri * scale, fp16 ----------------
__global__ void k_qt(const float* __restrict__ att, const float* __restrict__ pri) {
    int lane = threadIdx.x & 31;
    int h = threadIdx.x >> 5;
    int node = blockIdx.x * 32 + lane;
    if (node >= N_NODES) return;

    const float4* qp = (const float4*)(g_kqv + (1 * NH + h) * (N_NODES * DK) + node * DK);
    float4 q0 = qp[0], q1 = qp[1], q2 = qp[2], q3 = qp[3];

    __half* outb = g_qt_h + ((size_t)h * N_NODES + node) * (TE * DK);
    for (int t = 0; t < TE; t++) {
        float pv = pri[t * NH + h] * 0.25f;
        const float4* A = (const float4*)att + (t * NH + h) * 64;   // lane-uniform broadcasts
        __align__(16) __half2 hq[8];
#pragma unroll
        for (int ip = 0; ip < 8; ip++) {
            int i0 = 2 * ip;
            int i1 = 2 * ip + 1;
            float4 a0 = A[i0 * 4 + 0], a1 = A[i0 * 4 + 1], a2 = A[i0 * 4 + 2], a3 = A[i0 * 4 + 3];
            float r0 = a0.x * q0.x + a0.y * q0.y + a0.z * q0.z + a0.w * q0.w
                     + a1.x * q1.x + a1.y * q1.y + a1.z * q1.z + a1.w * q1.w
                     + a2.x * q2.x + a2.y * q2.y + a2.z * q2.z + a2.w * q2.w
                     + a3.x * q3.x + a3.y * q3.y + a3.z * q3.z + a3.w * q3.w;
            float4 b0 = A[i1 * 4 + 0], b1 = A[i1 * 4 + 1], b2 = A[i1 * 4 + 2], b3 = A[i1 * 4 + 3];
            float r1 = b0.x * q0.x + b0.y * q0.y + b0.z * q0.z + b0.w * q0.w
                     + b1.x * q1.x + b1.y * q1.y + b1.z * q1.z + b1.w * q1.w
                     + b2.x * q2.x + b2.y * q2.y + b2.z * q2.z + b2.w * q2.w
                     + b3.x * q3.x + b3.y * q3.y + b3.z * q3.z + b3.w * q3.w;
            hq[ip] = __floats2half2_rn(r0 * pv, r1 * pv);
        }
        *((uint4*)(outb + t * DK))     = *((uint4*)&hq[0]);
        *((uint4*)(outb + t * DK + 8)) = *((uint4*)&hq[4]);
    }
}

// ---------------- relation projection (v only): vt[et*NH+h, n] = v@msg, fp16 ----------------
__global__ void k_relproj(const float* __restrict__ msg) {
    int lane = threadIdx.x & 31;
    int h = threadIdx.x >> 5;
    int node = blockIdx.x * 32 + lane;
    if (node >= N_NODES) return;

    float vreg[16];
    const float4* vp = (const float4*)(g_kqv + (2 * NH + h) * (N_NODES * DK) + node * DK);
#pragma unroll
    for (int c = 0; c < 4; c++) {
        float4 b = vp[c];
        vreg[c * 4 + 0] = b.x; vreg[c * 4 + 1] = b.y; vreg[c * 4 + 2] = b.z; vreg[c * 4 + 3] = b.w;
    }

    for (int t = 0; t < TE; t++) {
        float vt[16];
#pragma unroll
        for (int z = 0; z < 16; z++) vt[z] = 0.f;
        const float4* M = (const float4*)msg + (t * NH + h) * 64;
#pragma unroll
        for (int i = 0; i < 16; i++) {
            float vi = vreg[i];
#pragma unroll
            for (int jc = 0; jc < 4; jc++) {
                float4 mm = M[i * 4 + jc];
                vt[jc * 4 + 0] += vi * mm.x; vt[jc * 4 + 1] += vi * mm.y;
                vt[jc * 4 + 2] += vi * mm.z; vt[jc * 4 + 3] += vi * mm.w;
            }
        }
        __align__(16) __half2 hv[8];
#pragma unroll
        for (int c = 0; c < 8; c++) {
            hv[c] = __floats2half2_rn(vt[2 * c], vt[2 * c + 1]);
        }
        size_t off = ((size_t)(t * NH + h) * N_NODES + node) * DK;
        *((uint4*)&g_vt_h[off])     = *((uint4*)&hv[0]);
        *((uint4*)&g_vt_h[off + 8]) = *((uint4*)&hv[4]);
    }
}

// ---------------- edge attention logits: k (L2-resident) . qt (L1-local) ----------------
__global__ void k_logits() {
    int p = blockIdx.x * blockDim.x + threadIdx.x;
    int h = blockIdx.y;
    if (p >= N_EDGES) return;
    int e = g_eidx[p];
    int et = e >> 16;
    int s = e & 0xFFFF;
    int d = g_dst_s[p];
    const __half2* kk = (const __half2*)(g_k_h + ((size_t)h * N_NODES + s) * DK);
    const __half2* qt = (const __half2*)(g_qt_h + (((size_t)h * N_NODES + d) * TE + et) * DK);
    float acc = 0.f;
#pragma unroll
    for (int c = 0; c < 8; c++) {
        float2 a = __half22float2(kk[c]);
        float2 b = __half22float2(qt[c]);
        acc += a.x * b.x + a.y * b.y;
    }
    g_elog[(size_t)h * N_EDGES + p] = acc;
    atomicMax(&g_mkey[d * NH + h], fkey(acc));   // order-independent -> deterministic
}

// ---------------- edge softmax + aggregation (exp once; 4 edges in flight) ----------------
__global__ void k_agg() {
    int d = blockIdx.x;
    int h = threadIdx.x >> 5;
    int lane = threadIdx.x & 31;
    int rs = g_rowstart[d];
    int deg = g_rowstart[d + 1] - rs;
    int j2 = lane & 7;
    int quad = lane >> 3;
    float* el = g_elog + (size_t)h * N_EDGES + rs;

    if (deg == 0) {
        if (lane < 8) ((float2*)&g_agg[d * DHID + h * DK])[j2] = make_float2(0.f, 0.f);
        return;
    }
    float m = fdec(g_mkey[d * NH + h]);
    float s = 0.f;
    for (int i = lane; i < deg; i += 32) {
        float v = __expf(el[i] - m);
        el[i] = v;
        s += v;
    }
#pragma unroll
    for (int o = 16; o > 0; o >>= 1) s += __shfl_xor_sync(0xffffffffu, s, o);
    float inv = 1.f / s;
    float ax = 0.f, ay = 0.f;
    for (int i = quad; i < deg; i += 4) {
        float a = el[i];
        int e = g_eidx[rs + i];
        int et = e >> 16;
        int sn = e & 0xFFFF;
        __half2 v = *((const __half2*)(g_vt_h + ((size_t)(et * NH + h) * N_NODES + sn) * DK) + j2);
        float2 vf = __half22float2(v);
        ax += a * vf.x;
        ay += a * vf.y;
    }
#pragma unroll
    for (int o = 16; o >= 8; o >>= 1) {
        ax += __shfl_xor_sync(0xffffffffu, ax, o);
        ay += __shfl_xor_sync(0xffffffffu, ay, o);
    }
    if (lane < 8) ((float2*)&g_agg[d * DHID + h * DK])[j2] = make_float2(ax * inv, ay * inv);
}

// ---------------- output: relu(agg @ Wa[t] + x @ loop + bias) ----------------
__global__ void k_out(const float* __restrict__ x, const float* __restrict__ loopw,
                      const float* __restrict__ bias, float* __restrict__ out) {
    int t = blockIdx.y;
    int cnt = g_tstart[t + 1] - g_tstart[t];
    int tile = blockIdx.x * 64;
    if (tile >= cnt) return;

    __shared__ __align__(16) float xs[64][132];
    __shared__ __align__(16) float ws[16][128];
    __shared__ int rows[64];

    int tid = threadIdx.x;
    if (tid < 64) {
        int r = tile + tid;
        rows[tid] = (r < cnt) ? g_node_order[g_tstart[t] + r] : -1;
    }
    __syncthreads();

    int tc = tid & 31;
    int tr = tid >> 5;
    float acc[8][4];
#pragma unroll
    for (int m = 0; m < 8; m++) {
#pragma unroll
        for (int c = 0; c < 4; c++) acc[m][c] = 0.f;
    }

    for (int ph = 0; ph < 2; ph++) {
        const float* A = (ph == 0) ? g_agg : x;
        const float* W = (ph == 0) ? (g_W + (3 * TN + t) * (DIN * DHID)) : loopw;
        __syncthreads();
        for (int i = tid; i < 64 * 32; i += 256) {
            int nr = i >> 5;
            int c4 = i & 31;
            float4 v = make_float4(0.f, 0.f, 0.f, 0.f);
            int g = rows[nr];
            if (g >= 0) v = ((const float4*)A)[g * 32 + c4];
            *((float4*)&xs[nr][c4 * 4]) = v;
        }
        for (int kk = 0; kk < 8; kk++) {
            __syncthreads();
            for (int i = tid; i < 512; i += 256) {
                int r = i >> 5;
                int c4 = i & 31;
                ((float4*)&ws[r][0])[c4] = ((const float4*)(W + (kk * 16 + r) * DHID))[c4];
            }
            __syncthreads();
#pragma unroll
            for (int k2 = 0; k2 < 16; k2++) {
                float4 b = *((const float4*)&ws[k2][tc * 4]);
#pragma unroll
                for (int m = 0; m < 8; m++) {
                    float a = xs[tr * 8 + m][kk * 16 + k2];
                    acc[m][0] += a * b.x; acc[m][1] += a * b.y;
                    acc[m][2] += a * b.z; acc[m][3] += a * b.w;
                }
            }
        }
    }

    float4 bv = *((const float4*)&bias[tc * 4]);
#pragma unroll
    for (int m = 0; m < 8; m++) {
        int g = rows[tr * 8 + m];
        if (g >= 0) {
            float4 o;
            o.x = fmaxf(acc[m][0] + bv.x, 0.f);
            o.y = fmaxf(acc[m][1] + bv.y, 0.f);
            o.z = fmaxf(acc[m][2] + bv.z, 0.f);
            o.w = fmaxf(acc[m][3] + bv.w, 0.f);
            *((float4*)&out[g * DHID + tc * 4]) = o;
        }
    }
}

// ---------------- launch ----------------
extern "C" void kernel_launch(void* const* d_in, const int* in_sizes, int n_in,
                              void* d_out, int out_size) {
    const float* x     = (const float*)d_in[0];
    const int*   ntype = (const int*)d_in[1];
    const int*   src   = (const int*)d_in[2];
    const int*   dst   = (const int*)d_in[3];
    const int*   etype = (const int*)d_in[4];
    const float* wck   = (const float*)d_in[5];
    const float* wbk   = (const float*)d_in[6];
    const float* wcq   = (const float*)d_in[7];
    const float* wbq   = (const float*)d_in[8];
    const float* wcv   = (const float*)d_in[9];
    const float* wbv   = (const float*)d_in[10];
    const float* wca   = (const float*)d_in[11];
    const float* wba   = (const float*)d_in[12];
    const float* pri   = (const float*)d_in[13];
    const float* att   = (const float*)d_in[14];
    const float* msg   = (const float*)d_in[15];
    const float* loopw = (const float*)d_in[16];
    const float* bias  = (const float*)d_in[17];
    float* out = (float*)d_out;

    k_init<<<(N_NODES * NH + 255) / 256, 256>>>();
    k_prepW<<<(4 * TN * DIN * DHID + 255) / 256, 256>>>(wck, wbk, wcq, wbq, wcv, wbv, wca, wba);
    k_count<<<(N_EDGES + 255) / 256, 256>>>(ntype, dst);
    k_scanA<<<NCHUNK, 1024>>>();
    k_scanB<<<1, 32>>>();
    k_scanC<<<NCHUNK, 1024>>>();
    k_scatter<<<(N_EDGES + 255) / 256, 256>>>(ntype, src, dst, etype);
    k_proj<<<dim3((N_NODES + 63) / 64, TN), 256>>>(x);
    k_qt<<<(N_NODES + 31) / 32, 256>>>(att, pri);
    k_relproj<<<(N_NODES + 31) / 32, 256>>>(msg);
    k_logits<<<dim3((N_EDGES + 255) / 256, NH), 256>>>();
    k_agg<<<N_NODES, 256>>>();
    k_out<<<dim3((N_NODES + 63) / 64, TN), 256>>>(x, loopw, bias, out);
}

// round 9
// speedup vs baseline: 1.2099x; 1.0868x over previous
#include <cuda_runtime.h>
#include <cuda_fp16.h>
#include <cstdint>

#define N_NODES 50000
#define N_EDGES 800000
#define DIN 128
#define DHID 128
#define NH 8
#define DK 16
#define TN 8
#define TE 8
#define NB 4
#define NCHUNK ((N_NODES + 1023) / 1024)

// ---------------- scratch (static device memory; no allocations) ----------------
__device__ __half g_W_h[4 * TN * DIN * DHID];          // fp16 Wk,Wq,Wv,Wa for tensor cores
__device__ __half g_lw_hi[DIN * DHID];                 // loopw fp16 high part
__device__ __half g_lw_lo[DIN * DHID];                 // loopw fp16 residual
__device__ float  g_kqv[3 * NH * N_NODES * DK];        // k,q,v in [mat][h][n][16] layout
__device__ __half g_k_h[(size_t)NH * N_NODES * DK];    // k fp16 [h][n][16], 12.8 MB (L2-resident)
__device__ __half g_qt_h[(size_t)NH * N_NODES * TE * DK]; // (att@q)*pri*scale fp16 [h][n][et][16]
__device__ __half g_vt_h[(size_t)TE * NH * N_NODES * DK]; // v@msg fp16 [et*NH+h][n][16]
__device__ float  g_elog[(size_t)NH * N_EDGES];        // logits -> exp values [h][p]
__device__ int    g_mkey[N_NODES * NH];                // max logit per (dst,h), monotone int key
__device__ __half g_agg_h[N_NODES * DHID];             // aggregated messages fp16 [n][128]
__device__ int    g_deg[N_NODES];
__device__ int    g_rowstart[N_NODES + 1];
__device__ int    g_cursor[N_NODES];
__device__ int    g_eidx[N_EDGES];                     // (et<<16)|src, sorted by dst
__device__ int    g_dst_s[N_EDGES];                    // dst, sorted (CSR order)
__device__ int    g_node_order[N_NODES];
__device__ int    g_ncount[TN];
__device__ int    g_tstart[TN + 1];
__device__ int    g_tcur[TN];
__device__ int    g_part[NCHUNK];
__device__ int    g_chunkoff[NCHUNK];

// monotone float<->int key (order-preserving, so atomicMax is deterministic)
__device__ __forceinline__ int   fkey(float f) { int b = __float_as_int(f); return b >= 0 ? b : (b ^ 0x7FFFFFFF); }
__device__ __forceinline__ float fdec(int k)   { return __int_as_float(k >= 0 ? k : (k ^ 0x7FFFFFFF)); }

// ---------------- warp-mma helpers ----------------
__device__ __forceinline__ void ldsm_x4(unsigned& r0, unsigned& r1, unsigned& r2, unsigned& r3, unsigned addr) {
    asm volatile("ldmatrix.sync.aligned.m8n8.x4.shared.b16 {%0,%1,%2,%3}, [%4];"
                 : "=r"(r0), "=r"(r1), "=r"(r2), "=r"(r3) : "r"(addr));
}
__device__ __forceinline__ void ldsm_x4_t(unsigned& r0, unsigned& r1, unsigned& r2, unsigned& r3, unsigned addr) {
    asm volatile("ldmatrix.sync.aligned.m8n8.x4.trans.shared.b16 {%0,%1,%2,%3}, [%4];"
                 : "=r"(r0), "=r"(r1), "=r"(r2), "=r"(r3) : "r"(addr));
}
__device__ __forceinline__ void mma16816(float* c, unsigned a0, unsigned a1, unsigned a2, unsigned a3,
                                         unsigned b0, unsigned b1) {
    asm volatile("mma.sync.aligned.m16n8k16.row.col.f32.f16.f16.f32 "
                 "{%0,%1,%2,%3},{%4,%5,%6,%7},{%8,%9},{%0,%1,%2,%3};"
                 : "+f"(c[0]), "+f"(c[1]), "+f"(c[2]), "+f"(c[3])
                 : "r"(a0), "r"(a1), "r"(a2), "r"(a3), "r"(b0), "r"(b1));
}

// ---------------- init: zero counters, -inf max keys ----------------
__global__ void k_init() {
    int i = blockIdx.x * blockDim.x + threadIdx.x;
    if (i < N_NODES) g_deg[i] = 0;
    if (i < TN) g_ncount[i] = 0;
    if (i < N_NODES * NH) g_mkey[i] = 0x80000000;   // INT_MIN <= every key
}

// ---------------- build per-type weight matrices W[t] = comp[t] @ basis (fp16) ----------------
__global__ void k_prepW(const float* __restrict__ ck, const float* __restrict__ bk,
                        const float* __restrict__ cq, const float* __restrict__ bq,
                        const float* __restrict__ cv, const float* __restrict__ bv,
                        const float* __restrict__ ca, const float* __restrict__ ba) {
    int idx = blockIdx.x * blockDim.x + threadIdx.x;           // 4 * 8 * 16384
    if (idx >= 4 * TN * DIN * DHID) return;
    int m  = idx >> 17;           // matrix id
    int r  = idx & 131071;
    int t  = r >> 14;             // type
    int io = r & 16383;
    const float* comp;
    const float* basis;
    if (m == 0)      { comp = ck; basis = bk; }
    else if (m == 1) { comp = cq; basis = bq; }
    else if (m == 2) { comp = cv; basis = bv; }
    else             { comp = ca; basis = ba; }
    float acc = 0.f;
#pragma unroll
    for (int b = 0; b < NB; b++)
        acc += comp[t * NB + b] * basis[b * (DIN * DHID) + io];
    g_W_h[idx] = __float2half(acc);
}

// ---------------- loopw split into fp16 hi + lo ----------------
__global__ void k_prepL(const float* __restrict__ loopw) {
    int i = blockIdx.x * blockDim.x + threadIdx.x;
    if (i >= DIN * DHID) return;
    float w = loopw[i];
    __half hi = __float2half(w);
    g_lw_hi[i] = hi;
    g_lw_lo[i] = __float2half(w - __half2float(hi));
}

// ---------------- counts: node types + in-degrees ----------------
__global__ void k_count(const int* __restrict__ ntype, const int* __restrict__ dst) {
    int i = blockIdx.x * blockDim.x + threadIdx.x;
    if (i < N_NODES) atomicAdd(&g_ncount[ntype[i]], 1);
    if (i < N_EDGES) atomicAdd(&g_deg[dst[i]], 1);
}

// ---------------- parallel scan phase A ----------------
__global__ void k_scanA() {
    __shared__ int wsum[32];
    int tid = threadIdx.x;
    int chunk = blockIdx.x;
    int i = chunk * 1024 + tid;
    int v = (i < N_NODES) ? g_deg[i] : 0;
    int lane = tid & 31, w = tid >> 5;
    int s = v;
#pragma unroll
    for (int o = 1; o < 32; o <<= 1) {
        int t = __shfl_up_sync(0xffffffffu, s, o);
        if (lane >= o) s += t;
    }
    if (lane == 31) wsum[w] = s;
    __syncthreads();
    if (w == 0) {
        int x = wsum[lane];
#pragma unroll
        for (int o = 1; o < 32; o <<= 1) {
            int t = __shfl_up_sync(0xffffffffu, x, o);
            if (lane >= o) x += t;
        }
        wsum[lane] = x;
    }
    __syncthreads();
    int excl = s - v + (w > 0 ? wsum[w - 1] : 0);
    if (i < N_NODES) g_rowstart[i] = excl;
    if (tid == 1023) g_part[chunk] = excl + v;
}

// ---------------- scan phase B ----------------
__global__ void k_scanB() {
    if (threadIdx.x == 0) {
        int acc = 0;
        for (int c = 0; c < NCHUNK; c++) { g_chunkoff[c] = acc; acc += g_part[c]; }
        g_rowstart[N_NODES] = N_EDGES;
        int a2 = 0;
        g_tstart[0] = 0;
        for (int t = 0; t < TN; t++) { a2 += g_ncount[t]; g_tstart[t + 1] = a2; }
        for (int t = 0; t < TN; t++) g_tcur[t] = g_tstart[t];
    }
}

// ---------------- scan phase C ----------------
__global__ void k_scanC() {
    int i = blockIdx.x * 1024 + threadIdx.x;
    if (i < N_NODES) {
        int r = g_rowstart[i] + g_chunkoff[blockIdx.x];
        g_rowstart[i] = r;
        g_cursor[i] = r;
    }
}

// ---------------- scatter ----------------
__global__ void k_scatter(const int* __restrict__ ntype, const int* __restrict__ src,
                          const int* __restrict__ dst, const int* __restrict__ etype) {
    int i = blockIdx.x * blockDim.x + threadIdx.x;
    if (i < N_NODES) {
        int t = ntype[i];
        int p = atomicAdd(&g_tcur[t], 1);
        g_node_order[p] = i;
    }
    if (i < N_EDGES) {
        int d = dst[i];
        int p = atomicAdd(&g_cursor[d], 1);
        g_eidx[p] = (etype[i] << 16) | src[i];    // N_NODES < 65536
        g_dst_s[p] = d;
    }
}

// ---------------- projection GEMM via tensor cores (fp16 in, fp32 accum) ----------------
// tile: 64 nodes x 128 out, K=128 in 2 chunks of 64. 8 warps = 4M x 2N.
__global__ void k_proj(const float* __restrict__ x) {
    int t = blockIdx.y;
    int cnt = g_tstart[t + 1] - g_tstart[t];
    int tile = blockIdx.x * 64;
    if (tile >= cnt) return;

    __shared__ __align__(16) __half As[64][136];
    __shared__ __align__(16) __half Ws[64][136];
    __shared__ int rows[64];

    int tid = threadIdx.x;
    if (tid < 64) {
        int r = tile + tid;
        rows[tid] = (r < cnt) ? g_node_order[g_tstart[t] + r] : -1;
    }
    __syncthreads();

    // gathered x rows -> fp16 smem
    for (int i = tid; i < 64 * 32; i += 256) {
        int nr = i >> 5;
        int c4 = i & 31;
        float4 v = make_float4(0.f, 0.f, 0.f, 0.f);
        int g = rows[nr];
        if (g >= 0) v = ((const float4*)x)[g * 32 + c4];
        *((__half2*)&As[nr][c4 * 4])     = __floats2half2_rn(v.x, v.y);
        *((__half2*)&As[nr][c4 * 4 + 2]) = __floats2half2_rn(v.z, v.w);
    }

    int w = tid >> 5;
    int lane = tid & 31;
    int mr = (w & 3) * 16;            // M offset of this warp
    int nc = (w >> 2) * 64;           // N offset of this warp
    int lrow = (lane & 7) + ((lane >> 3) & 1) * 8;   // ldmatrix source row (within 16)
    int lcol8 = (lane >> 4) * 8;                     // ldmatrix 8-col group

    int r0 = mr + (lane >> 2);        // accumulator row (mma layout)
    int cb = nc + (lane & 3) * 2;     // accumulator col base

    for (int mat = 0; mat < 3; mat++) {
        float acc[8][4];
#pragma unroll
        for (int nt = 0; nt < 8; nt++) {
#pragma unroll
            for (int c = 0; c < 4; c++) acc[nt][c] = 0.f;
        }

        const __half* W = g_W_h + (mat * TN + t) * (DIN * DHID);
        for (int kc = 0; kc < 2; kc++) {
            __syncthreads();   // protects Ws rewrite (and As on first pass)
            for (int i = tid; i < 64 * 16; i += 256) {
                int r = i >> 4;
                int c8 = i & 15;
                *((uint4*)&Ws[r][c8 * 8]) = ((const uint4*)(W + (kc * 64 + r) * DHID))[c8];
            }
            __syncthreads();
#pragma unroll
            for (int ks = 0; ks < 4; ks++) {
                unsigned a0, a1, a2, a3;
                unsigned aAddr = (unsigned)__cvta_generic_to_shared(
                    &As[mr + lrow][kc * 64 + ks * 16 + lcol8]);
                ldsm_x4(a0, a1, a2, a3, aAddr);
#pragma unroll
                for (int np = 0; np < 4; np++) {
                    unsigned b0, b1, b2, b3;
                    unsigned bAddr = (unsigned)__cvta_generic_to_shared(
                        &Ws[ks * 16 + lrow][nc + np * 16 + lcol8]);
                    ldsm_x4_t(b0, b1, b2, b3, bAddr);
                    mma16816(acc[np * 2],     a0, a1, a2, a3, b0, b1);
                    mma16816(acc[np * 2 + 1], a0, a1, a2, a3, b2, b3);
                }
            }
        }
        // store: [mat][h][n][16] fp32 (+ fp16 k copy)
        int g0 = rows[r0];
        int g1 = rows[r0 + 8];
        float* outb = g_kqv + mat * NH * (N_NODES * DK);
#pragma unroll
        for (int nt = 0; nt < 8; nt++) {
            int c = cb + nt * 8;
            int h = c >> 4;
            int j = c & 15;
            if (g0 >= 0) {
                *((float2*)&outb[(h * N_NODES + g0) * DK + j]) = make_float2(acc[nt][0], acc[nt][1]);
                if (mat == 0) {
                    *((__half2*)&g_k_h[((size_t)h * N_NODES + g0) * DK + j]) =
                        __floats2half2_rn(acc[nt][0], acc[nt][1]);
                }
            }
            if (g1 >= 0) {
                *((float2*)&outb[(h * N_NODES + g1) * DK + j]) = make_float2(acc[nt][2], acc[nt][3]);
                if (mat == 0) {
                    *((__half2*)&g_k_h[((size_t)h * N_NODES + g1) * DK + j]) =
                        __floats2half2_rn(acc[nt][2], acc[nt][3]);
                }
            }
        }
    }
}

// ---------------- qt: qt[h,n,et,:] = (att[et,h] @ q[n,h]) * pri * scale, fp16 ----------------
__global__ void k_qt(const float* __restrict__ att, const float* __restrict__ pri) {
    int lane = threadIdx.x & 31;
    int h = threadIdx.x >> 5;
    int node = blockIdx.x * 32 + lane;
    if (node >= N_NODES) return;

    const float4* qp = (const float4*)(g_kqv + (1 * NH + h) * (N_NODES * DK) + node * DK);
    float4 q0 = qp[0], q1 = qp[1], q2 = qp[2], q3 = qp[3];

    __half* outb = g_qt_h + ((size_t)h * N_NODES + node) * (TE * DK);
    for (int t = 0; t < TE; t++) {
        float pv = pri[t * NH + h] * 0.25f;
        const float4* A = (const float4*)att + (t * NH + h) * 64;   // lane-uniform broadcasts
        __align__(16) __half2 hq[8];
#pragma unroll
        for (int ip = 0; ip < 8; ip++) {
            int i0 = 2 * ip;
            int i1 = 2 * ip + 1;
            float4 a0 = A[i0 * 4 + 0], a1 = A[i0 * 4 + 1], a2 = A[i0 * 4 + 2], a3 = A[i0 * 4 + 3];
            float r0 = a0.x * q0.x + a0.y * q0.y + a0.z * q0.z + a0.w * q0.w
                     + a1.x * q1.x + a1.y * q1.y + a1.z * q1.z + a1.w * q1.w
                     + a2.x * q2.x + a2.y * q2.y + a2.z * q2.z + a2.w * q2.w
                     + a3.x * q3.x + a3.y * q3.y + a3.z * q3.z + a3.w * q3.w;
            float4 b0 = A[i1 * 4 + 0], b1 = A[i1 * 4 + 1], b2 = A[i1 * 4 + 2], b3 = A[i1 * 4 + 3];
            float r1 = b0.x * q0.x + b0.y * q0.y + b0.z * q0.z + b0.w * q0.w
                     + b1.x * q1.x + b1.y * q1.y + b1.z * q1.z + b1.w * q1.w
                     + b2.x * q2.x + b2.y * q2.y + b2.z * q2.z + b2.w * q2.w
                     + b3.x * q3.x + b3.y * q3.y + b3.z * q3.z + b3.w * q3.w;
            hq[ip] = __floats2half2_rn(r0 * pv, r1 * pv);
        }
        *((uint4*)(outb + t * DK))     = *((uint4*)&hq[0]);
        *((uint4*)(outb + t * DK + 8)) = *((uint4*)&hq[4]);
    }
}

// ---------------- relation projection (v only): vt[et*NH+h, n] = v@msg, fp16 ----------------
__global__ void k_relproj(const float* __restrict__ msg) {
    int lane = threadIdx.x & 31;
    int h = threadIdx.x >> 5;
    int node = blockIdx.x * 32 + lane;
    if (node >= N_NODES) return;

    float vreg[16];
    const float4* vp = (const float4*)(g_kqv + (2 * NH + h) * (N_NODES * DK) + node * DK);
#pragma unroll
    for (int c = 0; c < 4; c++) {
        float4 b = vp[c];
        vreg[c * 4 + 0] = b.x; vreg[c * 4 + 1] = b.y; vreg[c * 4 + 2] = b.z; vreg[c * 4 + 3] = b.w;
    }

    for (int t = 0; t < TE; t++) {
        float vt[16];
#pragma unroll
        for (int z = 0; z < 16; z++) vt[z] = 0.f;
        const float4* M = (const float4*)msg + (t * NH + h) * 64;
#pragma unroll
        for (int i = 0; i < 16; i++) {
            float vi = vreg[i];
#pragma unroll
            for (int jc = 0; jc < 4; jc++) {
                float4 mm = M[i * 4 + jc];
                vt[jc * 4 + 0] += vi * mm.x; vt[jc * 4 + 1] += vi * mm.y;
                vt[jc * 4 + 2] += vi * mm.z; vt[jc * 4 + 3] += vi * mm.w;
            }
        }
        __align__(16) __half2 hv[8];
#pragma unroll
        for (int c = 0; c < 8; c++) {
            hv[c] = __floats2half2_rn(vt[2 * c], vt[2 * c + 1]);
        }
        size_t off = ((size_t)(t * NH + h) * N_NODES + node) * DK;
        *((uint4*)&g_vt_h[off])     = *((uint4*)&hv[0]);
        *((uint4*)&g_vt_h[off + 8]) = *((uint4*)&hv[4]);
    }
}

// ---------------- edge attention logits: k (L2-resident) . qt (L1-local) ----------------
__global__ void k_logits() {
    int p = blockIdx.x * blockDim.x + threadIdx.x;
    int h = blockIdx.y;
    if (p >= N_EDGES) return;
    int e = g_eidx[p];
    int et = e >> 16;
    int s = e & 0xFFFF;
    int d = g_dst_s[p];
    const __half2* kk = (const __half2*)(g_k_h + ((size_t)h * N_NODES + s) * DK);
    const __half2* qt = (const __half2*)(g_qt_h + (((size_t)h * N_NODES + d) * TE + et) * DK);
    float acc = 0.f;
#pragma unroll
    for (int c = 0; c < 8; c++) {
        float2 a = __half22float2(kk[c]);
        float2 b = __half22float2(qt[c]);
        acc += a.x * b.x + a.y * b.y;
    }
    g_elog[(size_t)h * N_EDGES + p] = acc;
    atomicMax(&g_mkey[d * NH + h], fkey(acc));   // order-independent -> deterministic
}

// ---------------- edge softmax + aggregation (exp once; 4 edges in flight) ----------------
__global__ void k_agg() {
    int d = blockIdx.x;
    int h = threadIdx.x >> 5;
    int lane = threadIdx.x & 31;
    int rs = g_rowstart[d];
    int deg = g_rowstart[d + 1] - rs;
    int j2 = lane & 7;
    int quad = lane >> 3;
    float* el = g_elog + (size_t)h * N_EDGES + rs;

    if (deg == 0) {
        if (lane < 8) ((__half2*)&g_agg_h[d * DHID + h * DK])[j2] = __floats2half2_rn(0.f, 0.f);
        return;
    }
    float m = fdec(g_mkey[d * NH + h]);
    float s = 0.f;
    for (int i = lane; i < deg; i += 32) {
        float v = __expf(el[i] - m);
        el[i] = v;
        s += v;
    }
#pragma unroll
    for (int o = 16; o > 0; o >>= 1) s += __shfl_xor_sync(0xffffffffu, s, o);
    float inv = 1.f / s;
    float ax = 0.f, ay = 0.f;
    for (int i = quad; i < deg; i += 4) {
        float a = el[i];
        int e = g_eidx[rs + i];
        int et = e >> 16;
        int sn = e & 0xFFFF;
        __half2 v = *((const __half2*)(g_vt_h + ((size_t)(et * NH + h) * N_NODES + sn) * DK) + j2);
        float2 vf = __half22float2(v);
        ax += a * vf.x;
        ay += a * vf.y;
    }
#pragma unroll
    for (int o = 16; o >= 8; o >>= 1) {
        ax += __shfl_xor_sync(0xffffffffu, ax, o);
        ay += __shfl_xor_sync(0xffffffffu, ay, o);
    }
    if (lane < 8) ((__half2*)&g_agg_h[d * DHID + h * DK])[j2] = __floats2half2_rn(ax * inv, ay * inv);
}

// ---------------- output via tensor cores: relu(agg@Wa[t] + x@loop + bias) ----------------
// 4 K=128 phases: (agg, Wa_h), (x_hi, lw_hi), (x_hi, lw_lo), (x_lo, lw_hi).
// split-fp16 product for x@loopw keeps error ~1e-7; agg@Wa contributes ~0.4% of output.
__global__ void k_out(const float* __restrict__ x, const float* __restrict__ bias,
                      float* __restrict__ out) {
    int t = blockIdx.y;
    int cnt = g_tstart[t + 1] - g_tstart[t];
    int tile = blockIdx.x * 64;
    if (tile >= cnt) return;

    __shared__ __align__(16) __half As[64][136];
    __shared__ __align__(16) __half Ws[64][136];
    __shared__ int rows[64];

    int tid = threadIdx.x;
    if (tid < 64) {
        int r = tile + tid;
        rows[tid] = (r < cnt) ? g_node_order[g_tstart[t] + r] : -1;
    }
    __syncthreads();

    int w = tid >> 5;
    int lane = tid & 31;
    int mr = (w & 3) * 16;
    int nc = (w >> 2) * 64;
    int lrow = (lane & 7) + ((lane >> 3) & 1) * 8;
    int lcol8 = (lane >> 4) * 8;
    int r0 = mr + (lane >> 2);
    int cb = nc + (lane & 3) * 2;

    float acc[8][4];
#pragma unroll
    for (int nt = 0; nt < 8; nt++) {
#pragma unroll
        for (int c = 0; c < 4; c++) acc[nt][c] = 0.f;
    }

    for (int ph = 0; ph < 4; ph++) {
        // ---- A refill (phase 2 reuses x_hi from phase 1) ----
        if (ph != 2) {
            __syncthreads();
            if (ph == 0) {
                for (int i = tid; i < 64 * 16; i += 256) {
                    int r = i >> 4;
                    int c8 = i & 15;
                    uint4 v = make_uint4(0u, 0u, 0u, 0u);
                    int g = rows[r];
                    if (g >= 0) v = ((const uint4*)&g_agg_h[g * DHID])[c8];
                    *((uint4*)&As[r][c8 * 8]) = v;
                }
            } else {
                for (int i = tid; i < 64 * 32; i += 256) {
                    int r = i >> 5;
                    int c4 = i & 31;
                    float4 v = make_float4(0.f, 0.f, 0.f, 0.f);
                    int g = rows[r];
                    if (g >= 0) v = ((const float4*)x)[g * 32 + c4];
                    __half2 h0 = __floats2half2_rn(v.x, v.y);
                    __half2 h1 = __floats2half2_rn(v.z, v.w);
                    if (ph == 3) {   // residual: lo = fp16(x - hi)
                        float2 f0 = __half22float2(h0);
                        float2 f1 = __half22float2(h1);
                        h0 = __floats2half2_rn(v.x - f0.x, v.y - f0.y);
                        h1 = __floats2half2_rn(v.z - f1.x, v.w - f1.y);
                    }
                    *((__half2*)&As[r][c4 * 4])     = h0;
                    *((__half2*)&As[r][c4 * 4 + 2]) = h1;
                }
            }
        }
        const __half* B = (ph == 0) ? (g_W_h + (3 * TN + t) * (DIN * DHID))
                        : (ph == 2) ? g_lw_lo : g_lw_hi;
        for (int kc = 0; kc < 2; kc++) {
            __syncthreads();
            for (int i = tid; i < 64 * 16; i += 256) {
                int r = i >> 4;
                int c8 = i & 15;
                *((uint4*)&Ws[r][c8 * 8]) = ((const uint4*)(B + (kc * 64 + r) * DHID))[c8];
            }
            __syncthreads();
#pragma unroll
            for (int ks = 0; ks < 4; ks++) {
                unsigned a0, a1, a2, a3;
                unsigned aAddr = (unsigned)__cvta_generic_to_shared(
                    &As[mr + lrow][kc * 64 + ks * 16 + lcol8]);
                ldsm_x4(a0, a1, a2, a3, aAddr);
#pragma unroll
                for (int np = 0; np < 4; np++) {
                    unsigned b0, b1, b2, b3;
                    unsigned bAddr = (unsigned)__cvta_generic_to_shared(
                        &Ws[ks * 16 + lrow][nc + np * 16 + lcol8]);
                    ldsm_x4_t(b0, b1, b2, b3, bAddr);
                    mma16816(acc[np * 2],     a0, a1, a2, a3, b0, b1);
                    mma16816(acc[np * 2 + 1], a0, a1, a2, a3, b2, b3);
                }
            }
        }
    }

    int g0 = rows[r0];
    int g1 = rows[r0 + 8];
#pragma unroll
    for (int nt = 0; nt < 8; nt++) {
        int c = cb + nt * 8;
        float2 bv = *((const float2*)&bias[c]);
        if (g0 >= 0) {
            *((float2*)&out[g0 * DHID + c]) =
                make_float2(fmaxf(acc[nt][0] + bv.x, 0.f), fmaxf(acc[nt][1] + bv.y, 0.f));
        }
        if (g1 >= 0) {
            *((float2*)&out[g1 * DHID + c]) =
                make_float2(fmaxf(acc[nt][2] + bv.x, 0.f), fmaxf(acc[nt][3] + bv.y, 0.f));
        }
    }
}

// ---------------- launch ----------------
extern "C" void kernel_launch(void* const* d_in, const int* in_sizes, int n_in,
                              void* d_out, int out_size) {
    const float* x     = (const float*)d_in[0];
    const int*   ntype = (const int*)d_in[1];
    const int*   src   = (const int*)d_in[2];
    const int*   dst   = (const int*)d_in[3];
    const int*   etype = (const int*)d_in[4];
    const float* wck   = (const float*)d_in[5];
    const float* wbk   = (const float*)d_in[6];
    const float* wcq   = (const float*)d_in[7];
    const float* wbq   = (const float*)d_in[8];
    const float* wcv   = (const float*)d_in[9];
    const float* wbv   = (const float*)d_in[10];
    const float* wca   = (const float*)d_in[11];
    const float* wba   = (const float*)d_in[12];
    const float* pri   = (const float*)d_in[13];
    const float* att   = (const float*)d_in[14];
    const float* msg   = (const float*)d_in[15];
    const float* loopw = (const float*)d_in[16];
    const float* bias  = (const float*)d_in[17];
    float* out = (float*)d_out;

    k_init<<<(N_NODES * NH + 255) / 256, 256>>>();
    k_prepW<<<(4 * TN * DIN * DHID + 255) / 256, 256>>>(wck, wbk, wcq, wbq, wcv, wbv, wca, wba);
    k_prepL<<<(DIN * DHID + 255) / 256, 256>>>(loopw);
    k_count<<<(N_EDGES + 255) / 256, 256>>>(ntype, dst);
    k_scanA<<<NCHUNK, 1024>>>();
    k_scanB<<<1, 32>>>();
    k_scanC<<<NCHUNK, 1024>>>();
    k_scatter<<<(N_EDGES + 255) / 256, 256>>>(ntype, src, dst, etype);
    k_proj<<<dim3((N_NODES + 63) / 64, TN), 256>>>(x);
    k_qt<<<(N_NODES + 31) / 32, 256>>>(att, pri);
    k_relproj<<<(N_NODES + 31) / 32, 256>>>(msg);
    k_logits<<<dim3((N_EDGES + 255) / 256, NH), 256>>>();
    k_agg<<<N_NODES, 256>>>();
    k_out<<<dim3((N_NODES + 63) / 64, TN), 256>>>(x, bias, out);
}

// round 10
// speedup vs baseline: 1.8620x; 1.5389x over previous
#include <cuda_runtime.h>
#include <cuda_fp16.h>
#include <cstdint>

#define N_NODES 50000
#define N_EDGES 800000
#define DIN 128
#define DHID 128
#define NH 8
#define DK 16
#define TN 8
#define TE 8
#define NB 4
#define NCHUNK ((N_NODES + 1023) / 1024)

// ---------------- scratch (static device memory; no allocations) ----------------
__device__ __half g_W_h[4 * TN * DIN * DHID];          // fp16 Wk,Wq,Wv,Wa for tensor cores
__device__ __half g_lw_hi[DIN * DHID];                 // loopw fp16 high part
__device__ __half g_lw_lo[DIN * DHID];                 // loopw fp16 residual
__device__ __half g_kqv_h[3 * NH * N_NODES * DK];      // k,q,v fp16 [mat][h][n][16] (38.4 MB)
__device__ __half g_qt_h[(size_t)NH * N_NODES * TE * DK]; // (att@q)*pri*scale fp16 [h][n][et][16]
__device__ __half g_vt_h[(size_t)NH * N_NODES * TE * DK]; // v@msg fp16 [h][n][et][16]
__device__ float  g_elog[(size_t)NH * N_EDGES];        // logits -> exp values [h][p]
__device__ int    g_mkey[N_NODES * NH];                // max logit per (dst,h), monotone int key
__device__ __half g_agg_h[N_NODES * DHID];             // aggregated messages fp16 [n][128]
__device__ int    g_deg[N_NODES];
__device__ int    g_rowstart[N_NODES + 1];
__device__ int    g_cursor[N_NODES];
__device__ int    g_eidx[N_EDGES];                     // (et<<16)|src, sorted by dst
__device__ int    g_dst_s[N_EDGES];                    // dst, sorted (CSR order)
__device__ int    g_node_order[N_NODES];
__device__ int    g_ncount[TN];
__device__ int    g_tstart[TN + 1];
__device__ int    g_tcur[TN];
__device__ int    g_part[NCHUNK];
__device__ int    g_chunkoff[NCHUNK];

// monotone float<->int key (order-preserving, so atomicMax is deterministic)
__device__ __forceinline__ int   fkey(float f) { int b = __float_as_int(f); return b >= 0 ? b : (b ^ 0x7FFFFFFF); }
__device__ __forceinline__ float fdec(int k)   { return __int_as_float(k >= 0 ? k : (k ^ 0x7FFFFFFF)); }

// ---------------- warp-mma helpers ----------------
__device__ __forceinline__ void ldsm_x4(unsigned& r0, unsigned& r1, unsigned& r2, unsigned& r3, unsigned addr) {
    asm volatile("ldmatrix.sync.aligned.m8n8.x4.shared.b16 {%0,%1,%2,%3}, [%4];"
                 : "=r"(r0), "=r"(r1), "=r"(r2), "=r"(r3) : "r"(addr));
}
__device__ __forceinline__ void ldsm_x4_t(unsigned& r0, unsigned& r1, unsigned& r2, unsigned& r3, unsigned addr) {
    asm volatile("ldmatrix.sync.aligned.m8n8.x4.trans.shared.b16 {%0,%1,%2,%3}, [%4];"
                 : "=r"(r0), "=r"(r1), "=r"(r2), "=r"(r3) : "r"(addr));
}
__device__ __forceinline__ void mma16816(float* c, unsigned a0, unsigned a1, unsigned a2, unsigned a3,
                                         unsigned b0, unsigned b1) {
    asm volatile("mma.sync.aligned.m16n8k16.row.col.f32.f16.f16.f32 "
                 "{%0,%1,%2,%3},{%4,%5,%6,%7},{%8,%9},{%0,%1,%2,%3};"
                 : "+f"(c[0]), "+f"(c[1]), "+f"(c[2]), "+f"(c[3])
                 : "r"(a0), "r"(a1), "r"(a2), "r"(a3), "r"(b0), "r"(b1));
}

// ---------------- init: zero counters, -inf max keys ----------------
__global__ void k_init() {
    int i = blockIdx.x * blockDim.x + threadIdx.x;
    if (i < N_NODES) g_deg[i] = 0;
    if (i < TN) g_ncount[i] = 0;
    if (i < N_NODES * NH) g_mkey[i] = 0x80000000;   // INT_MIN <= every key
}

// ---------------- build per-type weight matrices W[t] = comp[t] @ basis (fp16) ----------------
__global__ void k_prepW(const float* __restrict__ ck, const float* __restrict__ bk,
                        const float* __restrict__ cq, const float* __restrict__ bq,
                        const float* __restrict__ cv, const float* __restrict__ bv,
                        const float* __restrict__ ca, const float* __restrict__ ba) {
    int idx = blockIdx.x * blockDim.x + threadIdx.x;           // 4 * 8 * 16384
    if (idx >= 4 * TN * DIN * DHID) return;
    int m  = idx >> 17;           // matrix id
    int r  = idx & 131071;
    int t  = r >> 14;             // type
    int io = r & 16383;
    const float* comp;
    const float* basis;
    if (m == 0)      { comp = ck; basis = bk; }
    else if (m == 1) { comp = cq; basis = bq; }
    else if (m == 2) { comp = cv; basis = bv; }
    else             { comp = ca; basis = ba; }
    float acc = 0.f;
#pragma unroll
    for (int b = 0; b < NB; b++)
        acc += comp[t * NB + b] * basis[b * (DIN * DHID) + io];
    g_W_h[idx] = __float2half(acc);
}

// ---------------- loopw split into fp16 hi + lo ----------------
__global__ void k_prepL(const float* __restrict__ loopw) {
    int i = blockIdx.x * blockDim.x + threadIdx.x;
    if (i >= DIN * DHID) return;
    float w = loopw[i];
    __half hi = __float2half(w);
    g_lw_hi[i] = hi;
    g_lw_lo[i] = __float2half(w - __half2float(hi));
}

// ---------------- counts: node types + in-degrees ----------------
__global__ void k_count(const int* __restrict__ ntype, const int* __restrict__ dst) {
    int i = blockIdx.x * blockDim.x + threadIdx.x;
    if (i < N_NODES) atomicAdd(&g_ncount[ntype[i]], 1);
    if (i < N_EDGES) atomicAdd(&g_deg[dst[i]], 1);
}

// ---------------- parallel scan phase A ----------------
__global__ void k_scanA() {
    __shared__ int wsum[32];
    int tid = threadIdx.x;
    int chunk = blockIdx.x;
    int i = chunk * 1024 + tid;
    int v = (i < N_NODES) ? g_deg[i] : 0;
    int lane = tid & 31, w = tid >> 5;
    int s = v;
#pragma unroll
    for (int o = 1; o < 32; o <<= 1) {
        int t = __shfl_up_sync(0xffffffffu, s, o);
        if (lane >= o) s += t;
    }
    if (lane == 31) wsum[w] = s;
    __syncthreads();
    if (w == 0) {
        int x = wsum[lane];
#pragma unroll
        for (int o = 1; o < 32; o <<= 1) {
            int t = __shfl_up_sync(0xffffffffu, x, o);
            if (lane >= o) x += t;
        }
        wsum[lane] = x;
    }
    __syncthreads();
    int excl = s - v + (w > 0 ? wsum[w - 1] : 0);
    if (i < N_NODES) g_rowstart[i] = excl;
    if (tid == 1023) g_part[chunk] = excl + v;
}

// ---------------- scan phase B ----------------
__global__ void k_scanB() {
    if (threadIdx.x == 0) {
        int acc = 0;
        for (int c = 0; c < NCHUNK; c++) { g_chunkoff[c] = acc; acc += g_part[c]; }
        g_rowstart[N_NODES] = N_EDGES;
        int a2 = 0;
        g_tstart[0] = 0;
        for (int t = 0; t < TN; t++) { a2 += g_ncount[t]; g_tstart[t + 1] = a2; }
        for (int t = 0; t < TN; t++) g_tcur[t] = g_tstart[t];
    }
}

// ---------------- scan phase C ----------------
__global__ void k_scanC() {
    int i = blockIdx.x * 1024 + threadIdx.x;
    if (i < N_NODES) {
        int r = g_rowstart[i] + g_chunkoff[blockIdx.x];
        g_rowstart[i] = r;
        g_cursor[i] = r;
    }
}

// ---------------- scatter ----------------
__global__ void k_scatter(const int* __restrict__ ntype, const int* __restrict__ src,
                          const int* __restrict__ dst, const int* __restrict__ etype) {
    int i = blockIdx.x * blockDim.x + threadIdx.x;
    if (i < N_NODES) {
        int t = ntype[i];
        int p = atomicAdd(&g_tcur[t], 1);
        g_node_order[p] = i;
    }
    if (i < N_EDGES) {
        int d = dst[i];
        int p = atomicAdd(&g_cursor[d], 1);
        g_eidx[p] = (etype[i] << 16) | src[i];    // N_NODES < 65536
        g_dst_s[p] = d;
    }
}

// ---------------- projection GEMM via tensor cores (fp16 in, fp32 accum, fp16 out) ----------------
// tile: 64 nodes x 128 out, K=128 in 2 chunks of 64. 8 warps = 4M x 2N.
__global__ void k_proj(const float* __restrict__ x) {
    int t = blockIdx.y;
    int cnt = g_tstart[t + 1] - g_tstart[t];
    int tile = blockIdx.x * 64;
    if (tile >= cnt) return;

    __shared__ __align__(16) __half As[64][136];
    __shared__ __align__(16) __half Ws[64][136];
    __shared__ int rows[64];

    int tid = threadIdx.x;
    if (tid < 64) {
        int r = tile + tid;
        rows[tid] = (r < cnt) ? g_node_order[g_tstart[t] + r] : -1;
    }
    __syncthreads();

    // gathered x rows -> fp16 smem
    for (int i = tid; i < 64 * 32; i += 256) {
        int nr = i >> 5;
        int c4 = i & 31;
        float4 v = make_float4(0.f, 0.f, 0.f, 0.f);
        int g = rows[nr];
        if (g >= 0) v = ((const float4*)x)[g * 32 + c4];
        *((__half2*)&As[nr][c4 * 4])     = __floats2half2_rn(v.x, v.y);
        *((__half2*)&As[nr][c4 * 4 + 2]) = __floats2half2_rn(v.z, v.w);
    }

    int w = tid >> 5;
    int lane = tid & 31;
    int mr = (w & 3) * 16;            // M offset of this warp
    int nc = (w >> 2) * 64;           // N offset of this warp
    int lrow = (lane & 7) + ((lane >> 3) & 1) * 8;   // ldmatrix source row (within 16)
    int lcol8 = (lane >> 4) * 8;                     // ldmatrix 8-col group

    int r0 = mr + (lane >> 2);        // accumulator row (mma layout)
    int cb = nc + (lane & 3) * 2;     // accumulator col base

    for (int mat = 0; mat < 3; mat++) {
        float acc[8][4];
#pragma unroll
        for (int nt = 0; nt < 8; nt++) {
#pragma unroll
            for (int c = 0; c < 4; c++) acc[nt][c] = 0.f;
        }

        const __half* W = g_W_h + (mat * TN + t) * (DIN * DHID);
        for (int kc = 0; kc < 2; kc++) {
            __syncthreads();   // protects Ws rewrite (and As on first pass)
            for (int i = tid; i < 64 * 16; i += 256) {
                int r = i >> 4;
                int c8 = i & 15;
                *((uint4*)&Ws[r][c8 * 8]) = ((const uint4*)(W + (kc * 64 + r) * DHID))[c8];
            }
            __syncthreads();
#pragma unroll
            for (int ks = 0; ks < 4; ks++) {
                unsigned a0, a1, a2, a3;
                unsigned aAddr = (unsigned)__cvta_generic_to_shared(
                    &As[mr + lrow][kc * 64 + ks * 16 + lcol8]);
                ldsm_x4(a0, a1, a2, a3, aAddr);
#pragma unroll
                for (int np = 0; np < 4; np++) {
                    unsigned b0, b1, b2, b3;
                    unsigned bAddr = (unsigned)__cvta_generic_to_shared(
                        &Ws[ks * 16 + lrow][nc + np * 16 + lcol8]);
                    ldsm_x4_t(b0, b1, b2, b3, bAddr);
                    mma16816(acc[np * 2],     a0, a1, a2, a3, b0, b1);
                    mma16816(acc[np * 2 + 1], a0, a1, a2, a3, b2, b3);
                }
            }
        }
        // store fp16 to [mat][h][n][16]
        int g0 = rows[r0];
        int g1 = rows[r0 + 8];
#pragma unroll
        for (int nt = 0; nt < 8; nt++) {
            int c = cb + nt * 8;
            int h = c >> 4;
            int j = c & 15;
            size_t base = (size_t)(mat * NH + h) * N_NODES;
            if (g0 >= 0) {
                *((__half2*)&g_kqv_h[(base + g0) * DK + j]) = __floats2half2_rn(acc[nt][0], acc[nt][1]);
            }
            if (g1 >= 0) {
                *((__half2*)&g_kqv_h[(base + g1) * DK + j]) = __floats2half2_rn(acc[nt][2], acc[nt][3]);
            }
        }
    }
}

// ---------------- qt & vt via tensor cores ----------------
// Per block: 64 nodes, one head. Two GEMMs [64x16]@[16x128]:
//   qt = q @ B_att  (B col et*16+j = att[et,h][:,j] * pri[et,h] * scale)
//   vt = v @ B_msg
// Output rows are node-contiguous 128-half vectors -> coalesced stores.
__global__ void k_qtvt(const float* __restrict__ att, const float* __restrict__ msg,
                       const float* __restrict__ pri) {
    int h = blockIdx.y;
    int tile = blockIdx.x * 64;
    int tid = threadIdx.x;

    __shared__ __align__(16) __half As[64][24];    // 64x16 A tile (stride 48B)
    __shared__ __align__(16) __half Bs[16][136];   // 16x128 B tile

    int w = tid >> 5;
    int lane = tid & 31;
    int mr = (w & 3) * 16;
    int nc = (w >> 2) * 64;
    int lrow = (lane & 7) + ((lane >> 3) & 1) * 8;
    int lcol8 = (lane >> 4) * 8;
    int r0 = mr + (lane >> 2);
    int cb = nc + (lane & 3) * 2;

    for (int ph = 0; ph < 2; ph++) {
        __syncthreads();   // protect As/Bs from previous phase's reads
        // A tile: q (mat 1) or v (mat 2), fp16 node-contiguous
        {
            const __half* src = g_kqv_h + (size_t)((ph == 0 ? 1 : 2) * NH + h) * N_NODES * DK;
            if (tid < 128) {
                int r = tid >> 1;
                int hc = tid & 1;
                int node = tile + r;
                uint4 v = make_uint4(0u, 0u, 0u, 0u);
                if (node < N_NODES) v = *((const uint4*)(src + (size_t)node * DK + hc * 8));
                *((uint4*)&As[r][hc * 8]) = v;
            }
        }
        // B tile: att*pri*scale or msg
        {
            const float* M = (ph == 0) ? att : msg;
            for (int e = tid; e < 16 * 128; e += 256) {
                int i = e >> 7;
                int c = e & 127;
                int et = c >> 4;
                int j = c & 15;
                float val = M[(et * NH + h) * 256 + i * 16 + j];
                if (ph == 0) val *= pri[et * NH + h] * 0.25f;
                Bs[i][c] = __float2half(val);
            }
        }
        __syncthreads();

        float acc[8][4];
#pragma unroll
        for (int nt = 0; nt < 8; nt++) {
#pragma unroll
            for (int c = 0; c < 4; c++) acc[nt][c] = 0.f;
        }
        unsigned a0, a1, a2, a3;
        unsigned aAddr = (unsigned)__cvta_generic_to_shared(&As[mr + lrow][lcol8]);
        ldsm_x4(a0, a1, a2, a3, aAddr);
#pragma unroll
        for (int np = 0; np < 4; np++) {
            unsigned b0, b1, b2, b3;
            unsigned bAddr = (unsigned)__cvta_generic_to_shared(&Bs[lrow][nc + np * 16 + lcol8]);
            ldsm_x4_t(b0, b1, b2, b3, bAddr);
            mma16816(acc[np * 2],     a0, a1, a2, a3, b0, b1);
            mma16816(acc[np * 2 + 1], a0, a1, a2, a3, b2, b3);
        }

        __half* outb = (ph == 0) ? g_qt_h : g_vt_h;
        int n0 = tile + r0;
        int n1 = tile + r0 + 8;
#pragma unroll
        for (int nt = 0; nt < 8; nt++) {
            int c = cb + nt * 8;
            if (n0 < N_NODES) {
                *((__half2*)&outb[((size_t)h * N_NODES + n0) * 128 + c]) =
                    __floats2half2_rn(acc[nt][0], acc[nt][1]);
            }
            if (n1 < N_NODES) {
                *((__half2*)&outb[((size_t)h * N_NODES + n1) * 128 + c]) =
                    __floats2half2_rn(acc[nt][2], acc[nt][3]);
            }
        }
    }
}

// ---------------- edge attention logits: k (L2-resident) . qt (near-local) ----------------
__global__ void k_logits() {
    int p = blockIdx.x * blockDim.x + threadIdx.x;
    int h = blockIdx.y;
    if (p >= N_EDGES) return;
    int e = g_eidx[p];
    int et = e >> 16;
    int s = e & 0xFFFF;
    int d = g_dst_s[p];
    const uint4* kk4 = (const uint4*)(g_kqv_h + ((size_t)h * N_NODES + s) * DK);
    const uint4* qt4 = (const uint4*)(g_qt_h + ((size_t)h * N_NODES + d) * 128 + et * DK);
    uint4 ka = kk4[0], kb = kk4[1];
    uint4 qa = qt4[0], qb = qt4[1];
    const __half2* kh = (const __half2*)&ka;
    const __half2* qh = (const __half2*)&qa;
    float acc = 0.f;
#pragma unroll
    for (int c = 0; c < 4; c++) {
        float2 a = __half22float2(kh[c]);
        float2 b = __half22float2(qh[c]);
        acc += a.x * b.x + a.y * b.y;
    }
    kh = (const __half2*)&kb;
    qh = (const __half2*)&qb;
#pragma unroll
    for (int c = 0; c < 4; c++) {
        float2 a = __half22float2(kh[c]);
        float2 b = __half22float2(qh[c]);
        acc += a.x * b.x + a.y * b.y;
    }
    g_elog[(size_t)h * N_EDGES + p] = acc;
    atomicMax(&g_mkey[d * NH + h], fkey(acc));   // order-independent -> deterministic
}

// ---------------- edge softmax + aggregation (exp once; 4 edges in flight) ----------------
__global__ void k_agg() {
    int d = blockIdx.x;
    int h = threadIdx.x >> 5;
    int lane = threadIdx.x & 31;
    int rs = g_rowstart[d];
    int deg = g_rowstart[d + 1] - rs;
    int j2 = lane & 7;
    int quad = lane >> 3;
    float* el = g_elog + (size_t)h * N_EDGES + rs;

    if (deg == 0) {
        if (lane < 8) ((__half2*)&g_agg_h[d * DHID + h * DK])[j2] = __floats2half2_rn(0.f, 0.f);
        return;
    }
    float m = fdec(g_mkey[d * NH + h]);
    float s = 0.f;
    for (int i = lane; i < deg; i += 32) {
        float v = __expf(el[i] - m);
        el[i] = v;
        s += v;
    }
#pragma unroll
    for (int o = 16; o > 0; o >>= 1) s += __shfl_xor_sync(0xffffffffu, s, o);
    float inv = 1.f / s;
    float ax = 0.f, ay = 0.f;
    for (int i = quad; i < deg; i += 4) {
        float a = el[i];
        int e = g_eidx[rs + i];
        int et = e >> 16;
        int sn = e & 0xFFFF;
        __half2 v = *((const __half2*)(g_vt_h + ((size_t)h * N_NODES + sn) * 128 + et * DK) + j2);
        float2 vf = __half22float2(v);
        ax += a * vf.x;
        ay += a * vf.y;
    }
#pragma unroll
    for (int o = 16; o >= 8; o >>= 1) {
        ax += __shfl_xor_sync(0xffffffffu, ax, o);
        ay += __shfl_xor_sync(0xffffffffu, ay, o);
    }
    if (lane < 8) ((__half2*)&g_agg_h[d * DHID + h * DK])[j2] = __floats2half2_rn(ax * inv, ay * inv);
}

// ---------------- output via tensor cores: relu(agg@Wa[t] + x@loop + bias) ----------------
// 4 K=128 phases: (agg, Wa_h), (x_hi, lw_hi), (x_hi, lw_lo), (x_lo, lw_hi).
__global__ void k_out(const float* __restrict__ x, const float* __restrict__ bias,
                      float* __restrict__ out) {
    int t = blockIdx.y;
    int cnt = g_tstart[t + 1] - g_tstart[t];
    int tile = blockIdx.x * 64;
    if (tile >= cnt) return;

    __shared__ __align__(16) __half As[64][136];
    __shared__ __align__(16) __half Ws[64][136];
    __shared__ int rows[64];

    int tid = threadIdx.x;
    if (tid < 64) {
        int r = tile + tid;
        rows[tid] = (r < cnt) ? g_node_order[g_tstart[t] + r] : -1;
    }
    __syncthreads();

    int w = tid >> 5;
    int lane = tid & 31;
    int mr = (w & 3) * 16;
    int nc = (w >> 2) * 64;
    int lrow = (lane & 7) + ((lane >> 3) & 1) * 8;
    int lcol8 = (lane >> 4) * 8;
    int r0 = mr + (lane >> 2);
    int cb = nc + (lane & 3) * 2;

    float acc[8][4];
#pragma unroll
    for (int nt = 0; nt < 8; nt++) {
#pragma unroll
        for (int c = 0; c < 4; c++) acc[nt][c] = 0.f;
    }

    for (int ph = 0; ph < 4; ph++) {
        if (ph != 2) {   // phase 2 reuses x_hi from phase 1
            __syncthreads();
            if (ph == 0) {
                for (int i = tid; i < 64 * 16; i += 256) {
                    int r = i >> 4;
                    int c8 = i & 15;
                    uint4 v = make_uint4(0u, 0u, 0u, 0u);
                    int g = rows[r];
                    if (g >= 0) v = ((const uint4*)&g_agg_h[g * DHID])[c8];
                    *((uint4*)&As[r][c8 * 8]) = v;
                }
            } else {
                for (int i = tid; i < 64 * 32; i += 256) {
                    int r = i >> 5;
                    int c4 = i & 31;
                    float4 v = make_float4(0.f, 0.f, 0.f, 0.f);
                    int g = rows[r];
                    if (g >= 0) v = ((const float4*)x)[g * 32 + c4];
                    __half2 h0 = __floats2half2_rn(v.x, v.y);
                    __half2 h1 = __floats2half2_rn(v.z, v.w);
                    if (ph == 3) {   // residual: lo = fp16(x - hi)
                        float2 f0 = __half22float2(h0);
                        float2 f1 = __half22float2(h1);
                        h0 = __floats2half2_rn(v.x - f0.x, v.y - f0.y);
                        h1 = __floats2half2_rn(v.z - f1.x, v.w - f1.y);
                    }
                    *((__half2*)&As[r][c4 * 4])     = h0;
                    *((__half2*)&As[r][c4 * 4 + 2]) = h1;
                }
            }
        }
        const __half* B = (ph == 0) ? (g_W_h + (3 * TN + t) * (DIN * DHID))
                        : (ph == 2) ? g_lw_lo : g_lw_hi;
        for (int kc = 0; kc < 2; kc++) {
            __syncthreads();
            for (int i = tid; i < 64 * 16; i += 256) {
                int r = i >> 4;
                int c8 = i & 15;
                *((uint4*)&Ws[r][c8 * 8]) = ((const uint4*)(B + (kc * 64 + r) * DHID))[c8];
            }
            __syncthreads();
#pragma unroll
            for (int ks = 0; ks < 4; ks++) {
                unsigned a0, a1, a2, a3;
                unsigned aAddr = (unsigned)__cvta_generic_to_shared(
                    &As[mr + lrow][kc * 64 + ks * 16 + lcol8]);
                ldsm_x4(a0, a1, a2, a3, aAddr);
#pragma unroll
                for (int np = 0; np < 4; np++) {
                    unsigned b0, b1, b2, b3;
                    unsigned bAddr = (unsigned)__cvta_generic_to_shared(
                        &Ws[ks * 16 + lrow][nc + np * 16 + lcol8]);
                    ldsm_x4_t(b0, b1, b2, b3, bAddr);
                    mma16816(acc[np * 2],     a0, a1, a2, a3, b0, b1);
                    mma16816(acc[np * 2 + 1], a0, a1, a2, a3, b2, b3);
                }
            }
        }
    }

    int g0 = rows[r0];
    int g1 = rows[r0 + 8];
#pragma unroll
    for (int nt = 0; nt < 8; nt++) {
        int c = cb + nt * 8;
        float2 bv = *((const float2*)&bias[c]);
        if (g0 >= 0) {
            *((float2*)&out[g0 * DHID + c]) =
                make_float2(fmaxf(acc[nt][0] + bv.x, 0.f), fmaxf(acc[nt][1] + bv.y, 0.f));
        }
        if (g1 >= 0) {
            *((float2*)&out[g1 * DHID + c]) =
                make_float2(fmaxf(acc[nt][2] + bv.x, 0.f), fmaxf(acc[nt][3] + bv.y, 0.f));
        }
    }
}

// ---------------- launch ----------------
extern "C" void kernel_launch(void* const* d_in, const int* in_sizes, int n_in,
                              void* d_out, int out_size) {
    const float* x     = (const float*)d_in[0];
    const int*   ntype = (const int*)d_in[1];
    const int*   src   = (const int*)d_in[2];
    const int*   dst   = (const int*)d_in[3];
    const int*   etype = (const int*)d_in[4];
    const float* wck   = (const float*)d_in[5];
    const float* wbk   = (const float*)d_in[6];
    const float* wcq   = (const float*)d_in[7];
    const float* wbq   = (const float*)d_in[8];
    const float* wcv   = (const float*)d_in[9];
    const float* wbv   = (const float*)d_in[10];
    const float* wca   = (const float*)d_in[11];
    const float* wba   = (const float*)d_in[12];
    const float* pri   = (const float*)d_in[13];
    const float* att   = (const float*)d_in[14];
    const float* msg   = (const float*)d_in[15];
    const float* loopw = (const float*)d_in[16];
    const float* bias  = (const float*)d_in[17];
    float* out = (float*)d_out;

    k_init<<<(N_NODES * NH + 255) / 256, 256>>>();
    k_prepW<<<(4 * TN * DIN * DHID + 255) / 256, 256>>>(wck, wbk, wcq, wbq, wcv, wbv, wca, wba);
    k_prepL<<<(DIN * DHID + 255) / 256, 256>>>(loopw);
    k_count<<<(N_EDGES + 255) / 256, 256>>>(ntype, dst);
    k_scanA<<<NCHUNK, 1024>>>();
    k_scanB<<<1, 32>>>();
    k_scanC<<<NCHUNK, 1024>>>();
    k_scatter<<<(N_EDGES + 255) / 256, 256>>>(ntype, src, dst, etype);
    k_proj<<<dim3((N_NODES + 63) / 64, TN), 256>>>(x);
    k_qtvt<<<dim3((N_NODES + 63) / 64, NH), 256>>>(att, msg, pri);
    k_logits<<<dim3((N_EDGES + 255) / 256, NH), 256>>>();
    k_agg<<<N_NODES, 256>>>();
    k_out<<<dim3((N_NODES + 63) / 64, TN), 256>>>(x, bias, out);
}

// round 11
// speedup vs baseline: 2.0243x; 1.0872x over previous
#include <cuda_runtime.h>
#include <cuda_fp16.h>
#include <cstdint>

#define N_NODES 50000
#define N_EDGES 800000
#define DIN 128
#define DHID 128
#define NH 8
#define DK 16
#define TN 8
#define TE 8
#define NB 4
#define NCHUNK ((N_NODES + 1023) / 1024)

// ---------------- scratch (static device memory; no allocations) ----------------
__device__ __half g_W_h[4 * TN * DIN * DHID];          // fp16 Wk,Wq,Wv,Wa for tensor cores
__device__ __half g_lw_hi[DIN * DHID];                 // loopw fp16 high part
__device__ __half g_lw_lo[DIN * DHID];                 // loopw fp16 residual
__device__ __half g_kqv_h[3 * NH * N_NODES * DK];      // k,q,v fp16 [mat][h][n][16] (38.4 MB)
__device__ __half g_qt_h[(size_t)NH * N_NODES * TE * DK]; // (att@q)*pri*scale fp16 [h][n][et][16]
__device__ __half g_vt_h[(size_t)NH * N_NODES * TE * DK]; // v@msg fp16 [h][n][et][16]
__device__ __half g_elog[(size_t)NH * N_EDGES];        // exp(logit) fp16 [h][p] (12.8MB, L2-resident)
__device__ __half g_agg_h[N_NODES * DHID];             // aggregated messages fp16 [n][128]
__device__ int    g_deg[N_NODES];
__device__ int    g_rowstart[N_NODES + 1];
__device__ int    g_cursor[N_NODES];
__device__ int    g_eidx[N_EDGES];                     // (et<<16)|src, sorted by dst
__device__ int    g_dst_s[N_EDGES];                    // dst, sorted (CSR order)
__device__ int    g_node_order[N_NODES];
__device__ int    g_ncount[TN];
__device__ int    g_tstart[TN + 1];
__device__ int    g_tcur[TN];
__device__ int    g_part[NCHUNK];
__device__ int    g_chunkoff[NCHUNK];

// ---------------- warp-mma helpers ----------------
__device__ __forceinline__ void ldsm_x4(unsigned& r0, unsigned& r1, unsigned& r2, unsigned& r3, unsigned addr) {
    asm volatile("ldmatrix.sync.aligned.m8n8.x4.shared.b16 {%0,%1,%2,%3}, [%4];"
                 : "=r"(r0), "=r"(r1), "=r"(r2), "=r"(r3) : "r"(addr));
}
__device__ __forceinline__ void ldsm_x4_t(unsigned& r0, unsigned& r1, unsigned& r2, unsigned& r3, unsigned addr) {
    asm volatile("ldmatrix.sync.aligned.m8n8.x4.trans.shared.b16 {%0,%1,%2,%3}, [%4];"
                 : "=r"(r0), "=r"(r1), "=r"(r2), "=r"(r3) : "r"(addr));
}
__device__ __forceinline__ void mma16816(float* c, unsigned a0, unsigned a1, unsigned a2, unsigned a3,
                                         unsigned b0, unsigned b1) {
    asm volatile("mma.sync.aligned.m16n8k16.row.col.f32.f16.f16.f32 "
                 "{%0,%1,%2,%3},{%4,%5,%6,%7},{%8,%9},{%0,%1,%2,%3};"
                 : "+f"(c[0]), "+f"(c[1]), "+f"(c[2]), "+f"(c[3])
                 : "r"(a0), "r"(a1), "r"(a2), "r"(a3), "r"(b0), "r"(b1));
}

// ---------------- init: zero counters ----------------
__global__ void k_init() {
    int i = blockIdx.x * blockDim.x + threadIdx.x;
    if (i < N_NODES) g_deg[i] = 0;
    if (i < TN) g_ncount[i] = 0;
}

// ---------------- build per-type weight matrices W[t] = comp[t] @ basis (fp16) ----------------
__global__ void k_prepW(const float* __restrict__ ck, const float* __restrict__ bk,
                        const float* __restrict__ cq, const float* __restrict__ bq,
                        const float* __restrict__ cv, const float* __restrict__ bv,
                        const float* __restrict__ ca, const float* __restrict__ ba) {
    int idx = blockIdx.x * blockDim.x + threadIdx.x;           // 4 * 8 * 16384
    if (idx >= 4 * TN * DIN * DHID) return;
    int m  = idx >> 17;           // matrix id
    int r  = idx & 131071;
    int t  = r >> 14;             // type
    int io = r & 16383;
    const float* comp;
    const float* basis;
    if (m == 0)      { comp = ck; basis = bk; }
    else if (m == 1) { comp = cq; basis = bq; }
    else if (m == 2) { comp = cv; basis = bv; }
    else             { comp = ca; basis = ba; }
    float acc = 0.f;
#pragma unroll
    for (int b = 0; b < NB; b++)
        acc += comp[t * NB + b] * basis[b * (DIN * DHID) + io];
    g_W_h[idx] = __float2half(acc);
}

// ---------------- loopw split into fp16 hi + lo ----------------
__global__ void k_prepL(const float* __restrict__ loopw) {
    int i = blockIdx.x * blockDim.x + threadIdx.x;
    if (i >= DIN * DHID) return;
    float w = loopw[i];
    __half hi = __float2half(w);
    g_lw_hi[i] = hi;
    g_lw_lo[i] = __float2half(w - __half2float(hi));
}

// ---------------- counts: node types + in-degrees ----------------
__global__ void k_count(const int* __restrict__ ntype, const int* __restrict__ dst) {
    int i = blockIdx.x * blockDim.x + threadIdx.x;
    if (i < N_NODES) atomicAdd(&g_ncount[ntype[i]], 1);
    if (i < N_EDGES) atomicAdd(&g_deg[dst[i]], 1);
}

// ---------------- parallel scan phase A ----------------
__global__ void k_scanA() {
    __shared__ int wsum[32];
    int tid = threadIdx.x;
    int chunk = blockIdx.x;
    int i = chunk * 1024 + tid;
    int v = (i < N_NODES) ? g_deg[i] : 0;
    int lane = tid & 31, w = tid >> 5;
    int s = v;
#pragma unroll
    for (int o = 1; o < 32; o <<= 1) {
        int t = __shfl_up_sync(0xffffffffu, s, o);
        if (lane >= o) s += t;
    }
    if (lane == 31) wsum[w] = s;
    __syncthreads();
    if (w == 0) {
        int x = wsum[lane];
#pragma unroll
        for (int o = 1; o < 32; o <<= 1) {
            int t = __shfl_up_sync(0xffffffffu, x, o);
            if (lane >= o) x += t;
        }
        wsum[lane] = x;
    }
    __syncthreads();
    int excl = s - v + (w > 0 ? wsum[w - 1] : 0);
    if (i < N_NODES) g_rowstart[i] = excl;
    if (tid == 1023) g_part[chunk] = excl + v;
}

// ---------------- scan phase B ----------------
__global__ void k_scanB() {
    if (threadIdx.x == 0) {
        int acc = 0;
        for (int c = 0; c < NCHUNK; c++) { g_chunkoff[c] = acc; acc += g_part[c]; }
        g_rowstart[N_NODES] = N_EDGES;
        int a2 = 0;
        g_tstart[0] = 0;
        for (int t = 0; t < TN; t++) { a2 += g_ncount[t]; g_tstart[t + 1] = a2; }
        for (int t = 0; t < TN; t++) g_tcur[t] = g_tstart[t];
    }
}

// ---------------- scan phase C ----------------
__global__ void k_scanC() {
    int i = blockIdx.x * 1024 + threadIdx.x;
    if (i < N_NODES) {
        int r = g_rowstart[i] + g_chunkoff[blockIdx.x];
        g_rowstart[i] = r;
        g_cursor[i] = r;
    }
}

// ---------------- scatter ----------------
__global__ void k_scatter(const int* __restrict__ ntype, const int* __restrict__ src,
                          const int* __restrict__ dst, const int* __restrict__ etype) {
    int i = blockIdx.x * blockDim.x + threadIdx.x;
    if (i < N_NODES) {
        int t = ntype[i];
        int p = atomicAdd(&g_tcur[t], 1);
        g_node_order[p] = i;
    }
    if (i < N_EDGES) {
        int d = dst[i];
        int p = atomicAdd(&g_cursor[d], 1);
        g_eidx[p] = (etype[i] << 16) | src[i];    // N_NODES < 65536
        g_dst_s[p] = d;
    }
}

// ---------------- projection GEMM via tensor cores (fp16 in, fp32 accum, fp16 out) ----------------
// tile: 64 nodes x 128 out, K=128 in 2 chunks of 64. 8 warps = 4M x 2N.
__global__ void k_proj(const float* __restrict__ x) {
    int t = blockIdx.y;
    int cnt = g_tstart[t + 1] - g_tstart[t];
    int tile = blockIdx.x * 64;
    if (tile >= cnt) return;

    __shared__ __align__(16) __half As[64][136];
    __shared__ __align__(16) __half Ws[64][136];
    __shared__ int rows[64];

    int tid = threadIdx.x;
    if (tid < 64) {
        int r = tile + tid;
        rows[tid] = (r < cnt) ? g_node_order[g_tstart[t] + r] : -1;
    }
    __syncthreads();

    // gathered x rows -> fp16 smem
    for (int i = tid; i < 64 * 32; i += 256) {
        int nr = i >> 5;
        int c4 = i & 31;
        float4 v = make_float4(0.f, 0.f, 0.f, 0.f);
        int g = rows[nr];
        if (g >= 0) v = ((const float4*)x)[g * 32 + c4];
        *((__half2*)&As[nr][c4 * 4])     = __floats2half2_rn(v.x, v.y);
        *((__half2*)&As[nr][c4 * 4 + 2]) = __floats2half2_rn(v.z, v.w);
    }

    int w = tid >> 5;
    int lane = tid & 31;
    int mr = (w & 3) * 16;            // M offset of this warp
    int nc = (w >> 2) * 64;           // N offset of this warp
    int lrow = (lane & 7) + ((lane >> 3) & 1) * 8;   // ldmatrix source row (within 16)
    int lcol8 = (lane >> 4) * 8;                     // ldmatrix 8-col group

    int r0 = mr + (lane >> 2);        // accumulator row (mma layout)
    int cb = nc + (lane & 3) * 2;     // accumulator col base

    for (int mat = 0; mat < 3; mat++) {
        float acc[8][4];
#pragma unroll
        for (int nt = 0; nt < 8; nt++) {
#pragma unroll
            for (int c = 0; c < 4; c++) acc[nt][c] = 0.f;
        }

        const __half* W = g_W_h + (mat * TN + t) * (DIN * DHID);
        for (int kc = 0; kc < 2; kc++) {
            __syncthreads();   // protects Ws rewrite (and As on first pass)
            for (int i = tid; i < 64 * 16; i += 256) {
                int r = i >> 4;
                int c8 = i & 15;
                *((uint4*)&Ws[r][c8 * 8]) = ((const uint4*)(W + (kc * 64 + r) * DHID))[c8];
            }
            __syncthreads();
#pragma unroll
            for (int ks = 0; ks < 4; ks++) {
                unsigned a0, a1, a2, a3;
                unsigned aAddr = (unsigned)__cvta_generic_to_shared(
                    &As[mr + lrow][kc * 64 + ks * 16 + lcol8]);
                ldsm_x4(a0, a1, a2, a3, aAddr);
#pragma unroll
                for (int np = 0; np < 4; np++) {
                    unsigned b0, b1, b2, b3;
                    unsigned bAddr = (unsigned)__cvta_generic_to_shared(
                        &Ws[ks * 16 + lrow][nc + np * 16 + lcol8]);
                    ldsm_x4_t(b0, b1, b2, b3, bAddr);
                    mma16816(acc[np * 2],     a0, a1, a2, a3, b0, b1);
                    mma16816(acc[np * 2 + 1], a0, a1, a2, a3, b2, b3);
                }
            }
        }
        // store fp16 to [mat][h][n][16]
        int g0 = rows[r0];
        int g1 = rows[r0 + 8];
#pragma unroll
        for (int nt = 0; nt < 8; nt++) {
            int c = cb + nt * 8;
            int h = c >> 4;
            int j = c & 15;
            size_t base = (size_t)(mat * NH + h) * N_NODES;
            if (g0 >= 0) {
                *((__half2*)&g_kqv_h[(base + g0) * DK + j]) = __floats2half2_rn(acc[nt][0], acc[nt][1]);
            }
            if (g1 >= 0) {
                *((__half2*)&g_kqv_h[(base + g1) * DK + j]) = __floats2half2_rn(acc[nt][2], acc[nt][3]);
            }
        }
    }
}

// ---------------- qt & vt via tensor cores ----------------
__global__ void k_qtvt(const float* __restrict__ att, const float* __restrict__ msg,
                       const float* __restrict__ pri) {
    int h = blockIdx.y;
    int tile = blockIdx.x * 64;
    int tid = threadIdx.x;

    __shared__ __align__(16) __half As[64][24];    // 64x16 A tile
    __shared__ __align__(16) __half Bs[16][136];   // 16x128 B tile

    int w = tid >> 5;
    int lane = tid & 31;
    int mr = (w & 3) * 16;
    int nc = (w >> 2) * 64;
    int lrow = (lane & 7) + ((lane >> 3) & 1) * 8;
    int lcol8 = (lane >> 4) * 8;
    int r0 = mr + (lane >> 2);
    int cb = nc + (lane & 3) * 2;

    for (int ph = 0; ph < 2; ph++) {
        __syncthreads();   // protect As/Bs from previous phase's reads
        {
            const __half* src = g_kqv_h + (size_t)((ph == 0 ? 1 : 2) * NH + h) * N_NODES * DK;
            if (tid < 128) {
                int r = tid >> 1;
                int hc = tid & 1;
                int node = tile + r;
                uint4 v = make_uint4(0u, 0u, 0u, 0u);
                if (node < N_NODES) v = *((const uint4*)(src + (size_t)node * DK + hc * 8));
                *((uint4*)&As[r][hc * 8]) = v;
            }
        }
        {
            const float* M = (ph == 0) ? att : msg;
            for (int e = tid; e < 16 * 128; e += 256) {
                int i = e >> 7;
                int c = e & 127;
                int et = c >> 4;
                int j = c & 15;
                float val = M[(et * NH + h) * 256 + i * 16 + j];
                if (ph == 0) val *= pri[et * NH + h] * 0.25f;
                Bs[i][c] = __float2half(val);
            }
        }
        __syncthreads();

        float acc[8][4];
#pragma unroll
        for (int nt = 0; nt < 8; nt++) {
#pragma unroll
            for (int c = 0; c < 4; c++) acc[nt][c] = 0.f;
        }
        unsigned a0, a1, a2, a3;
        unsigned aAddr = (unsigned)__cvta_generic_to_shared(&As[mr + lrow][lcol8]);
        ldsm_x4(a0, a1, a2, a3, aAddr);
#pragma unroll
        for (int np = 0; np < 4; np++) {
            unsigned b0, b1, b2, b3;
            unsigned bAddr = (unsigned)__cvta_generic_to_shared(&Bs[lrow][nc + np * 16 + lcol8]);
            ldsm_x4_t(b0, b1, b2, b3, bAddr);
            mma16816(acc[np * 2],     a0, a1, a2, a3, b0, b1);
            mma16816(acc[np * 2 + 1], a0, a1, a2, a3, b2, b3);
        }

        __half* outb = (ph == 0) ? g_qt_h : g_vt_h;
        int n0 = tile + r0;
        int n1 = tile + r0 + 8;
#pragma unroll
        for (int nt = 0; nt < 8; nt++) {
            int c = cb + nt * 8;
            if (n0 < N_NODES) {
                *((__half2*)&outb[((size_t)h * N_NODES + n0) * 128 + c]) =
                    __floats2half2_rn(acc[nt][0], acc[nt][1]);
            }
            if (n1 < N_NODES) {
                *((__half2*)&outb[((size_t)h * N_NODES + n1) * 128 + c]) =
                    __floats2half2_rn(acc[nt][2], acc[nt][3]);
            }
        }
    }
}

// ---------------- edge attention: exp(logit) directly (|logit| << 1, max-shift unnecessary) ----------------
__global__ void k_logits() {
    int p = blockIdx.x * blockDim.x + threadIdx.x;
    int h = blockIdx.y;
    if (p >= N_EDGES) return;
    int e = g_eidx[p];
    int et = e >> 16;
    int s = e & 0xFFFF;
    int d = g_dst_s[p];
    const uint4* kk4 = (const uint4*)(g_kqv_h + ((size_t)h * N_NODES + s) * DK);
    const uint4* qt4 = (const uint4*)(g_qt_h + ((size_t)h * N_NODES + d) * 128 + et * DK);
    uint4 ka = kk4[0], kb = kk4[1];
    uint4 qa = qt4[0], qb = qt4[1];
    const __half2* kh = (const __half2*)&ka;
    const __half2* qh = (const __half2*)&qa;
    float acc = 0.f;
#pragma unroll
    for (int c = 0; c < 4; c++) {
        float2 a = __half22float2(kh[c]);
        float2 b = __half22float2(qh[c]);
        acc += a.x * b.x + a.y * b.y;
    }
    kh = (const __half2*)&kb;
    qh = (const __half2*)&qb;
#pragma unroll
    for (int c = 0; c < 4; c++) {
        float2 a = __half22float2(kh[c]);
        float2 b = __half22float2(qh[c]);
        acc += a.x * b.x + a.y * b.y;
    }
    g_elog[(size_t)h * N_EDGES + p] = __float2half(__expf(acc));
}

// ---------------- edge softmax + aggregation (elog L2-resident; 4 edges in flight) ----------------
__global__ void k_agg() {
    int d = blockIdx.x;
    int h = threadIdx.x >> 5;
    int lane = threadIdx.x & 31;
    int rs = g_rowstart[d];
    int deg = g_rowstart[d + 1] - rs;
    int j2 = lane & 7;
    int quad = lane >> 3;
    const __half* el = g_elog + (size_t)h * N_EDGES + rs;

    if (deg == 0) {
        if (lane < 8) ((__half2*)&g_agg_h[d * DHID + h * DK])[j2] = __floats2half2_rn(0.f, 0.f);
        return;
    }
    // pass 1: denom (read-only, fp16 in L2)
    float s = 0.f;
    for (int i = lane; i < deg; i += 32) s += __half2float(el[i]);
#pragma unroll
    for (int o = 16; o > 0; o >>= 1) s += __shfl_xor_sync(0xffffffffu, s, o);
    float inv = 1.f / s;
    // pass 2: weighted vt gather (4 edges in flight; each lane covers 2 j's)
    float ax = 0.f, ay = 0.f;
    for (int i = quad; i < deg; i += 4) {
        float a = __half2float(el[i]);
        int e = g_eidx[rs + i];
        int et = e >> 16;
        int sn = e & 0xFFFF;
        __half2 v = *((const __half2*)(g_vt_h + ((size_t)h * N_NODES + sn) * 128 + et * DK) + j2);
        float2 vf = __half22float2(v);
        ax += a * vf.x;
        ay += a * vf.y;
    }
#pragma unroll
    for (int o = 16; o >= 8; o >>= 1) {
        ax += __shfl_xor_sync(0xffffffffu, ax, o);
        ay += __shfl_xor_sync(0xffffffffu, ay, o);
    }
    if (lane < 8) ((__half2*)&g_agg_h[d * DHID + h * DK])[j2] = __floats2half2_rn(ax * inv, ay * inv);
}

// ---------------- output via tensor cores: relu(agg@Wa[t] + x@loop + bias) ----------------
__global__ void k_out(const float* __restrict__ x, const float* __restrict__ bias,
                      float* __restrict__ out) {
    int t = blockIdx.y;
    int cnt = g_tstart[t + 1] - g_tstart[t];
    int tile = blockIdx.x * 64;
    if (tile >= cnt) return;

    __shared__ __align__(16) __half As[64][136];
    __shared__ __align__(16) __half Ws[64][136];
    __shared__ int rows[64];

    int tid = threadIdx.x;
    if (tid < 64) {
        int r = tile + tid;
        rows[tid] = (r < cnt) ? g_node_order[g_tstart[t] + r] : -1;
    }
    __syncthreads();

    int w = tid >> 5;
    int lane = tid & 31;
    int mr = (w & 3) * 16;
    int nc = (w >> 2) * 64;
    int lrow = (lane & 7) + ((lane >> 3) & 1) * 8;
    int lcol8 = (lane >> 4) * 8;
    int r0 = mr + (lane >> 2);
    int cb = nc + (lane & 3) * 2;

    float acc[8][4];
#pragma unroll
    for (int nt = 0; nt < 8; nt++) {
#pragma unroll
        for (int c = 0; c < 4; c++) acc[nt][c] = 0.f;
    }

    for (int ph = 0; ph < 4; ph++) {
        if (ph != 2) {   // phase 2 reuses x_hi from phase 1
            __syncthreads();
            if (ph == 0) {
                for (int i = tid; i < 64 * 16; i += 256) {
                    int r = i >> 4;
                    int c8 = i & 15;
                    uint4 v = make_uint4(0u, 0u, 0u, 0u);
                    int g = rows[r];
                    if (g >= 0) v = ((const uint4*)&g_agg_h[g * DHID])[c8];
                    *((uint4*)&As[r][c8 * 8]) = v;
                }
            } else {
                for (int i = tid; i < 64 * 32; i += 256) {
                    int r = i >> 5;
                    int c4 = i & 31;
                    float4 v = make_float4(0.f, 0.f, 0.f, 0.f);
                    int g = rows[r];
                    if (g >= 0) v = ((const float4*)x)[g * 32 + c4];
                    __half2 h0 = __floats2half2_rn(v.x, v.y);
                    __half2 h1 = __floats2half2_rn(v.z, v.w);
                    if (ph == 3) {   // residual: lo = fp16(x - hi)
                        float2 f0 = __half22float2(h0);
                        float2 f1 = __half22float2(h1);
                        h0 = __floats2half2_rn(v.x - f0.x, v.y - f0.y);
                        h1 = __floats2half2_rn(v.z - f1.x, v.w - f1.y);
                    }
                    *((__half2*)&As[r][c4 * 4])     = h0;
                    *((__half2*)&As[r][c4 * 4 + 2]) = h1;
                }
            }
        }
        const __half* B = (ph == 0) ? (g_W_h + (3 * TN + t) * (DIN * DHID))
                        : (ph == 2) ? g_lw_lo : g_lw_hi;
        for (int kc = 0; kc < 2; kc++) {
            __syncthreads();
            for (int i = tid; i < 64 * 16; i += 256) {
                int r = i >> 4;
                int c8 = i & 15;
                *((uint4*)&Ws[r][c8 * 8]) = ((const uint4*)(B + (kc * 64 + r) * DHID))[c8];
            }
            __syncthreads();
#pragma unroll
            for (int ks = 0; ks < 4; ks++) {
                unsigned a0, a1, a2, a3;
                unsigned aAddr = (unsigned)__cvta_generic_to_shared(
                    &As[mr + lrow][kc * 64 + ks * 16 + lcol8]);
                ldsm_x4(a0, a1, a2, a3, aAddr);
#pragma unroll
                for (int np = 0; np < 4; np++) {
                    unsigned b0, b1, b2, b3;
                    unsigned bAddr = (unsigned)__cvta_generic_to_shared(
                        &Ws[ks * 16 + lrow][nc + np * 16 + lcol8]);
                    ldsm_x4_t(b0, b1, b2, b3, bAddr);
                    mma16816(acc[np * 2],     a0, a1, a2, a3, b0, b1);
                    mma16816(acc[np * 2 + 1], a0, a1, a2, a3, b2, b3);
                }
            }
        }
    }

    int g0 = rows[r0];
    int g1 = rows[r0 + 8];
#pragma unroll
    for (int nt = 0; nt < 8; nt++) {
        int c = cb + nt * 8;
        float2 bv = *((const float2*)&bias[c]);
        if (g0 >= 0) {
            *((float2*)&out[g0 * DHID + c]) =
                make_float2(fmaxf(acc[nt][0] + bv.x, 0.f), fmaxf(acc[nt][1] + bv.y, 0.f));
        }
        if (g1 >= 0) {
            *((float2*)&out[g1 * DHID + c]) =
                make_float2(fmaxf(acc[nt][2] + bv.x, 0.f), fmaxf(acc[nt][3] + bv.y, 0.f));
        }
    }
}

// ---------------- launch ----------------
extern "C" void kernel_launch(void* const* d_in, const int* in_sizes, int n_in,
                              void* d_out, int out_size) {
    const float* x     = (const float*)d_in[0];
    const int*   ntype = (const int*)d_in[1];
    const int*   src   = (const int*)d_in[2];
    const int*   dst   = (const int*)d_in[3];
    const int*   etype = (const int*)d_in[4];
    const float* wck   = (const float*)d_in[5];
    const float* wbk   = (const float*)d_in[6];
    const float* wcq   = (const float*)d_in[7];
    const float* wbq   = (const float*)d_in[8];
    const float* wcv   = (const float*)d_in[9];
    const float* wbv   = (const float*)d_in[10];
    const float* wca   = (const float*)d_in[11];
    const float* wba   = (const float*)d_in[12];
    const float* pri   = (const float*)d_in[13];
    const float* att   = (const float*)d_in[14];
    const float* msg   = (const float*)d_in[15];
    const float* loopw = (const float*)d_in[16];
    const float* bias  = (const float*)d_in[17];
    float* out = (float*)d_out;

    k_init<<<(N_NODES + 255) / 256, 256>>>();
    k_prepW<<<(4 * TN * DIN * DHID + 255) / 256, 256>>>(wck, wbk, wcq, wbq, wcv, wbv, wca, wba);
    k_prepL<<<(DIN * DHID + 255) / 256, 256>>>(loopw);
    k_count<<<(N_EDGES + 255) / 256, 256>>>(ntype, dst);
    k_scanA<<<NCHUNK, 1024>>>();
    k_scanB<<<1, 32>>>();
    k_scanC<<<NCHUNK, 1024>>>();
    k_scatter<<<(N_EDGES + 255) / 256, 256>>>(ntype, src, dst, etype);
    k_proj<<<dim3((N_NODES + 63) / 64, TN), 256>>>(x);
    k_qtvt<<<dim3((N_NODES + 63) / 64, NH), 256>>>(att, msg, pri);
    k_logits<<<dim3((N_EDGES + 255) / 256, NH), 256>>>();
    k_agg<<<N_NODES, 256>>>();
    k_out<<<dim3((N_NODES + 63) / 64, TN), 256>>>(x, bias, out);
}